// round 9
// baseline (speedup 1.0000x reference)
#include <cuda_runtime.h>
#include <math.h>

#define NSIG   (1 << 22)              // 4194304 = HOP * N_FRAMES
#define NFR    16384
#define NBIN   513
#define HOPSZ  256
#define OUTLEN ((NFR - 1) * HOPSZ)    // 4194048
#define LVOFF(l) ((1 << 22) - (1 << (23 - (l))))

// ------------------------- device scratch (static per rules) -------------------
__device__ float  g_f0[NFR];
__device__ float  g_f0up[NSIG];
__device__ float  g_lv[NSIG];                    // pair-sum levels 1..22 packed
__device__ float  g_pulse[NSIG];
__device__ float  g_envTn[(size_t)NFR * NBIN];   // transposed log-envelopes [t][k]
__device__ float  g_envTp[(size_t)NFR * NBIN];
__device__ float  g_frames[(size_t)NFR * 1024];  // windowed synthesis frames
__device__ float2 g_tw[1024];                    // exp(-2*pi*i*t/1024)
__device__ float  g_w[1024];                     // hann window
__device__ float  g_wsqinv[256];                 // 1/sum_k w^2(n0+256k), interior

// ------------------------------- init tables -----------------------------------
__global__ void k_init() {
  int tid = threadIdx.x;                          // <<<1,1024>>>
  double ang = -2.0 * 3.14159265358979323846 * (double)tid / 1024.0;
  g_tw[tid] = make_float2((float)cos(ang), (float)sin(ang));
  g_w[tid] = 0.5f * (1.0f - cosf((float)tid * (6.28318530717958647692f / 1024.0f)));
  __syncthreads();
  if (tid < 256) {
    float w3 = g_w[tid + 768], w2 = g_w[tid + 512], w1 = g_w[tid + 256], w0 = g_w[tid];
    float a = w3 * w3;
    a += w2 * w2;
    a += w1 * w1;
    a += w0 * w0;
    g_wsqinv[tid] = 1.0f / fmaxf(a, 1e-11f);
  }
}

// --------------------- impulse train (bit-replicates JAX) ----------------------
__global__ void k_exp(const float* __restrict__ log_f0) {
  int i = blockIdx.x * blockDim.x + threadIdx.x;
  if (i < NFR) g_f0[i] = expf(log_f0[i]);
}

__global__ void k_interp() {
  int i = blockIdx.x * blockDim.x + threadIdx.x;
  float fi  = (float)i;
  float pos = __fsub_rn(__fdiv_rn(__fadd_rn(fi, 0.5f), 256.0f), 0.5f);
  pos = fminf(fmaxf(pos, 0.0f), 16383.0f);
  float flo = floorf(pos);
  int lo = (int)flo;
  int hi = lo + 1; if (hi > 16383) hi = 16383;
  float frac = __fsub_rn(pos, flo);
  float a = __fmul_rn(g_f0[lo], __fsub_rn(1.0f, frac));
  float b = __fmul_rn(g_f0[hi], frac);
  g_f0up[i] = __fadd_rn(a, b);
}

// pair-sum levels 1..10 (levels 1-2 in registers; identical __fadd_rn tree)
__global__ __launch_bounds__(256) void k_scan_lo() {
  __shared__ float s[256];
  int b = blockIdx.x, t = threadIdx.x;
  float4 x = ((const float4*)g_f0up)[b * 256 + t];
  float a0 = __fadd_rn(x.x, x.y);
  float a1 = __fadd_rn(x.z, x.w);
  float c  = __fadd_rn(a0, a1);
  ((float2*)(g_lv + LVOFF(1)))[b * 256 + t] = make_float2(a0, a1);
  g_lv[LVOFF(2) + b * 256 + t] = c;
  s[t] = c;
  __syncthreads();
  int n = 128;
  #pragma unroll
  for (int l = 3; l <= 10; l++) {
    float v = 0.0f;
    if (t < n) v = __fadd_rn(s[2 * t], s[2 * t + 1]);
    __syncthreads();
    if (t < n) { s[t] = v; g_lv[LVOFF(l) + b * n + t] = v; }
    __syncthreads();
    n >>= 1;
  }
}

// pair-sum levels 11..22, single block
__global__ __launch_bounds__(1024) void k_scan_hi() {
  __shared__ float s[4096];
  int t = threadIdx.x;
  #pragma unroll
  for (int q = 0; q < 4; q++) s[t + q * 1024] = g_lv[LVOFF(10) + t + q * 1024];
  __syncthreads();
  int n = 2048;
  for (int l = 11; l <= 22; l++) {
    float v0 = 0.0f, v1 = 0.0f;
    if (t < n)        v0 = __fadd_rn(s[2 * t], s[2 * t + 1]);
    if (t + 1024 < n) v1 = __fadd_rn(s[2 * (t + 1024)], s[2 * (t + 1024) + 1]);
    __syncthreads();
    if (t < n)        { s[t] = v0;        g_lv[LVOFF(l) + t] = v0; }
    if (t + 1024 < n) { s[t + 1024] = v1; g_lv[LVOFF(l) + t + 1024] = v1; }
    __syncthreads();
    n >>= 1;
  }
}

// cumsum closed form (jax associative_scan): left-fold of dyadic blocks of [0..n]
__device__ __forceinline__ float saw_at(int n) {
  int m = n + 1;
  float acc = 0.0f;
  bool first = true;
  int start = 0;
  #pragma unroll
  for (int l = 22; l >= 0; --l) {
    if (m & (1 << l)) {
      float v = (l == 0) ? g_f0up[start]
                         : g_lv[LVOFF(l) + (start >> l)];
      acc = first ? v : __fadd_rn(acc, v);
      first = false;
      start += (1 << l);
    }
  }
  float phase = __fdiv_rn(acc, 24000.0f);
  return __fsub_rn(phase, floorf(phase));
}

__global__ __launch_bounds__(256) void k_sawimp() {
  __shared__ float ssaw[257];
  int base = blockIdx.x * 256;
  int t = threadIdx.x;
  ssaw[t] = saw_at(base + t);
  if (t == 0) ssaw[256] = saw_at((base + 256) & (NSIG - 1));
  __syncthreads();
  float d = __fdiv_rn(g_f0up[base + t], 24000.0f);
  g_pulse[base + t] = __fadd_rn(__fsub_rn(ssaw[t], ssaw[t + 1]), d);
}

// --------- fused envelope transposes [513][16384] -> [16384][513] (both) --------
__global__ void k_transpose2(const float* __restrict__ in_n,
                             const float* __restrict__ in_p) {
  __shared__ float tile[32][33];
  int t0 = blockIdx.x * 32, k0 = blockIdx.y * 32;
  int x = t0 + threadIdx.x, y = k0 + threadIdx.y;
  int tx = t0 + threadIdx.y, kx = k0 + threadIdx.x;

  if (y < NBIN) tile[threadIdx.y][threadIdx.x] = in_n[(size_t)y * NFR + x];
  __syncthreads();
  if (kx < NBIN) g_envTn[(size_t)tx * NBIN + kx] = tile[threadIdx.x][threadIdx.y];
  __syncthreads();
  if (y < NBIN) tile[threadIdx.y][threadIdx.x] = in_p[(size_t)y * NFR + x];
  __syncthreads();
  if (kx < NBIN) g_envTp[(size_t)tx * NBIN + kx] = tile[threadIdx.x][threadIdx.y];
}

// ------------------------ register FFT building blocks -------------------------
__device__ __forceinline__ float2 cmul(float2 a, float2 b) {
  return make_float2(a.x * b.x - a.y * b.y, a.x * b.y + a.y * b.x);
}

// multiply by w (forward) or conj(w) (inverse)
template<bool INV>
__device__ __forceinline__ float2 cmulw(float2 a, float2 w) {
  if (!INV) return make_float2(a.x * w.x - a.y * w.y, a.x * w.y + a.y * w.x);
  else      return make_float2(a.x * w.x + a.y * w.y, a.y * w.x - a.x * w.y);
}

template<bool INV>
__device__ __forceinline__ void dft4(float2& x0, float2& x1, float2& x2, float2& x3) {
  float t0x = x0.x + x2.x, t0y = x0.y + x2.y;
  float t1x = x0.x - x2.x, t1y = x0.y - x2.y;
  float t2x = x1.x + x3.x, t2y = x1.y + x3.y;
  float t3x = x1.x - x3.x, t3y = x1.y - x3.y;
  x0 = make_float2(t0x + t2x, t0y + t2y);
  x2 = make_float2(t0x - t2x, t0y - t2y);
  if (!INV) {
    x1 = make_float2(t1x + t3y, t1y - t3x);
    x3 = make_float2(t1x - t3y, t1y + t3x);
  } else {
    x1 = make_float2(t1x - t3y, t1y + t3x);
    x3 = make_float2(t1x + t3y, t1y - t3x);
  }
}

template<bool INV>
__device__ __forceinline__ void dft8(float2 c[8]) {
  const float R2 = 0.70710678118654752f;
  float2 e0 = c[0], e1 = c[2], e2 = c[4], e3 = c[6];
  float2 o0 = c[1], o1 = c[3], o2 = c[5], o3 = c[7];
  dft4<INV>(e0, e1, e2, e3);
  dft4<INV>(o0, o1, o2, o3);
  float2 T1, T2, T3;
  if (!INV) {
    T1 = make_float2(R2 * (o1.x + o1.y), R2 * (o1.y - o1.x));
    T2 = make_float2(o2.y, -o2.x);
    T3 = make_float2(R2 * (o3.y - o3.x), R2 * (-o3.x - o3.y));
  } else {
    T1 = make_float2(R2 * (o1.x - o1.y), R2 * (o1.y + o1.x));
    T2 = make_float2(-o2.y, o2.x);
    T3 = make_float2(R2 * (-o3.y - o3.x), R2 * (o3.x - o3.y));
  }
  c[0] = make_float2(e0.x + o0.x, e0.y + o0.y);
  c[4] = make_float2(e0.x - o0.x, e0.y - o0.y);
  c[1] = make_float2(e1.x + T1.x, e1.y + T1.y);
  c[5] = make_float2(e1.x - T1.x, e1.y - T1.y);
  c[2] = make_float2(e2.x + T2.x, e2.y + T2.y);
  c[6] = make_float2(e2.x - T2.x, e2.y - T2.y);
  c[3] = make_float2(e3.x + T3.x, e3.y + T3.y);
  c[7] = make_float2(e3.x - T3.x, e3.y - T3.y);
}

template<bool INV>
__device__ __forceinline__ void dft16(float2 c[16]) {
  const float C1 = 0.92387953251128676f;
  const float S1 = 0.38268343236508977f;
  const float R2 = 0.70710678118654752f;
  const float SG = INV ? -1.0f : 1.0f;
  float2 e[8], o[8];
  #pragma unroll
  for (int q = 0; q < 8; q++) { e[q] = c[2 * q]; o[q] = c[2 * q + 1]; }
  dft8<INV>(e);
  dft8<INV>(o);
  const float2 w[8] = {
    make_float2(1.0f, 0.0f),  make_float2(C1, -SG * S1),
    make_float2(R2, -SG * R2), make_float2(S1, -SG * C1),
    make_float2(0.0f, -SG),   make_float2(-S1, -SG * C1),
    make_float2(-R2, -SG * R2), make_float2(-C1, -SG * S1)};
  #pragma unroll
  for (int r = 0; r < 8; r++) {
    float2 T = cmul(o[r], w[r]);
    c[r]     = make_float2(e[r].x + T.x, e[r].y + T.y);
    c[r + 8] = make_float2(e[r].x - T.x, e[r].y - T.y);
  }
}

__device__ __forceinline__ int SW(int i) { return i + (i >> 4); }
#define WSN 1088

// 1024-pt FFT, 128 threads/group. Input in A (caller synced), output in B.
// Stages: radix-8 (m=1), radix-8 (m=8), radix-16 (m=64, twiddle-free).
// Twiddles via independent table lookups (no serial cmul chain).
template<bool INV>
__device__ __forceinline__ void fftg(float2* A, float2* B, int t) {
  { // stage 1: j = t, m = 1
    float2 c[8];
    #pragma unroll
    for (int q = 0; q < 8; q++) c[q] = A[SW(t + 128 * q)];
    dft8<INV>(c);
    #pragma unroll
    for (int r = 1; r < 8; r++) c[r] = cmulw<INV>(c[r], __ldg(&g_tw[(r * t) & 1023]));
    #pragma unroll
    for (int r = 0; r < 8; r++) B[SW(8 * t + r)] = c[r];
  }
  __syncthreads();
  { // stage 2: j = t>>3, k = t&7, m = 8
    float2 c[8];
    #pragma unroll
    for (int q = 0; q < 8; q++) c[q] = B[SW(t + 128 * q)];
    dft8<INV>(c);
    int j = t >> 3, k = t & 7;
    #pragma unroll
    for (int r = 1; r < 8; r++) c[r] = cmulw<INV>(c[r], __ldg(&g_tw[(8 * j * r) & 1023]));
    int o = k + 64 * j;
    #pragma unroll
    for (int r = 0; r < 8; r++) A[SW(o + 8 * r)] = c[r];
  }
  __syncthreads();
  if (t < 64) { // stage 3: radix-16, j=0 -> no twiddles
    float2 c[16];
    #pragma unroll
    for (int q = 0; q < 16; q++) c[q] = A[SW(t + 64 * q)];
    dft16<INV>(c);
    #pragma unroll
    for (int r = 0; r < 16; r++) B[SW(t + 64 * r)] = c[r];
  }
  __syncthreads();
}

// ------------------------------ per-4-frame mega-kernel -------------------------
// Block: frames 4b..4b+3; group g owns pair (4b+2g, 4b+2g+1).
// Min-phase via Hilbert trick: C[k] = v[k] + i*h[k] with v the loaded log-env
// (kept in registers) and h from the packed FFT of the odd part of the cepstrum.
__global__ __launch_bounds__(256) void k_frames(const float* __restrict__ noise) {
  __shared__ __align__(16) float2 ws[2][2][WSN];

  int tid = threadIdx.x;
  int g  = tid >> 7;
  int tt = tid & 127;
  int f0 = 4 * blockIdx.x + 2 * g;
  int f1 = f0 + 1;
  float2* WA = ws[g][0];
  float2* WB = ws[g][1];

  // ---- phase 1: packed min-phase input (log-env of f0 + i*f1, symmetric) ----
  float v0r[5], v1r[5];
  #pragma unroll
  for (int q = 0; q < 8; q++) {
    int n = tt + 128 * q;
    int k = (n <= 512) ? n : 1024 - n;
    float a = g_envTp[(size_t)f0 * NBIN + k];
    float b = g_envTp[(size_t)f1 * NBIN + k];
    WA[SW(n)] = make_float2(a, b);
    if (q < 5) { v0r[q] = a; v1r[q] = b; }
  }
  __syncthreads();
  fftg<true>(WA, WB, tt);          // cep0*1024 in Re, cep1*1024 in Im

  // ---- phase 2: odd part of fold (s = +1 for 1..511, -1 for 513..1023) ----
  #pragma unroll
  for (int q = 0; q < 8; q++) {
    int n = tt + 128 * q;
    float s = (n == 0 || n == 512) ? 0.0f
            : (n < 512 ? (1.0f / 1024.0f) : (-1.0f / 1024.0f));
    float2 v = WB[SW(n)];
    WA[SW(n)] = make_float2(v.x * s, v.y * s);
  }
  __syncthreads();
  fftg<false>(WA, WB, tt);         // U[k] = -h1[k] + i*h0[k]

  // ---- phase 3: MP = exp(v) * (cos h + i sin h), registers only ----
  float2 MP0[5], MP1[5];
  #pragma unroll
  for (int q = 0; q < 5; q++) {
    int k = tt + 128 * q;
    if (k <= 512) {
      float2 U = WB[SW(k)];
      float h0 = U.y, h1 = -U.x;
      float sn, cs;
      float m0 = __expf(v0r[q]);
      __sincosf(h0, &sn, &cs);
      MP0[q] = make_float2(m0 * cs, m0 * sn);
      float m1 = __expf(v1r[q]);
      __sincosf(h1, &sn, &cs);
      MP1[q] = make_float2(m1 * cs, m1 * sn);
    }
  }

  // ---- phase 4: analysis FFT frame f0 (noise + i*pulse) ----
  #pragma unroll
  for (int q = 0; q < 8; q++) {
    int n = tt + 128 * q;
    int gi = f0 * 256 - 256 + n;
    if (gi < 0) gi = -gi;
    else if (gi >= NSIG) gi = 2 * NSIG - 2 - gi;
    float w = g_w[n];
    WA[SW(n)] = make_float2(noise[gi] * w, g_pulse[gi] * w);
  }
  __syncthreads();
  fftg<false>(WA, WB, tt);

  float2 S0[5];
  #pragma unroll
  for (int q = 0; q < 5; q++) {
    int k = tt + 128 * q;
    if (k <= 512) {
      float2 z1 = WB[SW(k)];
      float2 z2 = WB[SW((1024 - k) & 1023)];
      float en = __expf(g_envTn[(size_t)f0 * NBIN + k]);
      float2 N = make_float2(0.5f * (z1.x + z2.x) * en, 0.5f * (z1.y - z2.y) * en);
      float2 P = make_float2(0.5f * (z1.y + z2.y),      0.5f * (z2.x - z1.x));
      float2 PM = cmul(P, MP0[q]);
      S0[q] = make_float2(N.x + PM.x, N.y + PM.y);
    }
  }

  // ---- phase 5: analysis FFT frame f1, combine, packed synth spectrum ----
  #pragma unroll
  for (int q = 0; q < 8; q++) {
    int n = tt + 128 * q;
    int gi = f1 * 256 - 256 + n;
    if (gi < 0) gi = -gi;
    else if (gi >= NSIG) gi = 2 * NSIG - 2 - gi;
    float w = g_w[n];
    WA[SW(n)] = make_float2(noise[gi] * w, g_pulse[gi] * w);
  }
  __syncthreads();
  fftg<false>(WA, WB, tt);

  #pragma unroll
  for (int q = 0; q < 5; q++) {
    int k = tt + 128 * q;
    if (k <= 512) {
      float2 z1 = WB[SW(k)];
      float2 z2 = WB[SW((1024 - k) & 1023)];
      float en = __expf(g_envTn[(size_t)f1 * NBIN + k]);
      float2 N = make_float2(0.5f * (z1.x + z2.x) * en, 0.5f * (z1.y - z2.y) * en);
      float2 P = make_float2(0.5f * (z1.y + z2.y),      0.5f * (z2.x - z1.x));
      float2 PM = cmul(P, MP1[q]);
      float2 s1 = make_float2(N.x + PM.x, N.y + PM.y);
      float2 s0 = S0[q];
      if (k == 0 || k == 512) { s0.y = 0.0f; s1.y = 0.0f; }   // irfft drops these
      WA[SW(k)] = make_float2(s0.x - s1.y, s0.y + s1.x);
      if (k > 0 && k < 512)
        WA[SW(1024 - k)] = make_float2(s0.x + s1.y, s1.x - s0.y);
    }
  }
  __syncthreads();

  // ---- phase 6: packed synthesis iFFT, window, store both frames ----
  fftg<true>(WA, WB, tt);

  #pragma unroll
  for (int q = 0; q < 8; q++) {
    int n = tt + 128 * q;
    float wsc = (1.0f / 1024.0f) * g_w[n];
    float2 v = WB[SW(n)];
    g_frames[(size_t)f0 * 1024 + n] = v.x * wsc;
    g_frames[(size_t)f1 * 1024 + n] = v.y * wsc;
  }
}

// ----------------------------- overlap-add + wsq -------------------------------
__global__ void k_ola(float* __restrict__ out) {
  int i = blockIdx.x * blockDim.x + threadIdx.x;
  if (i >= OUTLEN) return;
  int p = i + 512;
  if (i >= 256 && i < OUTLEN - 256) {          // interior: exactly 4 full frames
    int jhi = p >> 8;
    int n0 = p & 255;
    const float* base = g_frames + (size_t)(jhi - 3) * 1024;
    float acc = base[n0 + 768];
    acc += base[1024 + n0 + 512];
    acc += base[2048 + n0 + 256];
    acc += base[3072 + n0];
    out[i] = acc * g_wsqinv[n0];
  } else {
    int jhi = p >> 8;
    int jlo = jhi - 3;
    if (jlo < 0) jlo = 0;
    if (jhi > NFR - 1) jhi = NFR - 1;
    float acc = 0.0f, wsq = 0.0f;
    for (int j = jlo; j <= jhi; j++) {
      int n = p - (j << 8);
      acc += g_frames[(size_t)j * 1024 + n];
      float w = g_w[n];
      wsq += w * w;
    }
    out[i] = acc / fmaxf(wsq, 1e-11f);
  }
}

// --------------------------------- launcher ------------------------------------
extern "C" void kernel_launch(void* const* d_in, const int* in_sizes, int n_in,
                              void* d_out, int out_size) {
  const float* log_f0  = (const float*)d_in[0];
  const float* env_noi = (const float*)d_in[1];
  const float* env_per = (const float*)d_in[2];
  const float* noise   = (const float*)d_in[3];
  float* out = (float*)d_out;

  k_init<<<1, 1024>>>();
  k_exp<<<NFR / 256, 256>>>(log_f0);
  k_interp<<<NSIG / 256, 256>>>();
  k_scan_lo<<<NSIG / 1024, 256>>>();
  k_scan_hi<<<1, 1024>>>();
  k_sawimp<<<NSIG / 256, 256>>>();
  dim3 tb(32, 32);
  dim3 tg(NFR / 32, (NBIN + 31) / 32);
  k_transpose2<<<tg, tb>>>(env_noi, env_per);
  k_frames<<<NFR / 4, 256>>>(noise);
  k_ola<<<(OUTLEN + 255) / 256, 256>>>(out);
}

// round 10
// speedup vs baseline: 1.2707x; 1.2707x over previous
#include <cuda_runtime.h>
#include <math.h>

#define NSIG   (1 << 22)              // 4194304 = HOP * N_FRAMES
#define NFR    16384
#define NBIN   513
#define HOPSZ  256
#define OUTLEN ((NFR - 1) * HOPSZ)    // 4194048
#define LVOFF(l) ((1 << 22) - (1 << (23 - (l))))

// ------------------------- device scratch (static per rules) -------------------
__device__ float  g_f0[NFR];
__device__ float  g_f0up[NSIG];
__device__ float  g_lv[NSIG];                    // pair-sum levels 1..22 packed
__device__ float  g_pulse[NSIG];
__device__ float  g_envTn[(size_t)NFR * NBIN];   // transposed log-envelopes [t][k]
__device__ float  g_envTp[(size_t)NFR * NBIN];
__device__ float  g_frames[(size_t)NFR * 1024];  // windowed synthesis frames
__device__ float2 g_tw[256];                     // exp(-2*pi*i*t/1024), t<256
__device__ float  g_w[1024];                     // hann window
__device__ float  g_wsqinv[256];                 // 1/sum_k w^2(n0+256k), interior

// ------------------------------- init tables -----------------------------------
__global__ void k_init() {
  int tid = threadIdx.x;                          // <<<1,1024>>>
  if (tid < 256) {
    double ang = -2.0 * 3.14159265358979323846 * (double)tid / 1024.0;
    g_tw[tid] = make_float2((float)cos(ang), (float)sin(ang));
  }
  g_w[tid] = 0.5f * (1.0f - cosf((float)tid * (6.28318530717958647692f / 1024.0f)));
  __syncthreads();
  if (tid < 256) {
    float w3 = g_w[tid + 768], w2 = g_w[tid + 512], w1 = g_w[tid + 256], w0 = g_w[tid];
    float a = w3 * w3;
    a += w2 * w2;
    a += w1 * w1;
    a += w0 * w0;
    g_wsqinv[tid] = 1.0f / fmaxf(a, 1e-11f);
  }
}

// --------------------- impulse train (bit-replicates JAX) ----------------------
__global__ void k_exp(const float* __restrict__ log_f0) {
  int i = blockIdx.x * blockDim.x + threadIdx.x;
  if (i < NFR) g_f0[i] = expf(log_f0[i]);
}

__global__ void k_interp() {
  int i = blockIdx.x * blockDim.x + threadIdx.x;
  float fi  = (float)i;
  float pos = __fsub_rn(__fdiv_rn(__fadd_rn(fi, 0.5f), 256.0f), 0.5f);
  pos = fminf(fmaxf(pos, 0.0f), 16383.0f);
  float flo = floorf(pos);
  int lo = (int)flo;
  int hi = lo + 1; if (hi > 16383) hi = 16383;
  float frac = __fsub_rn(pos, flo);
  float a = __fmul_rn(g_f0[lo], __fsub_rn(1.0f, frac));
  float b = __fmul_rn(g_f0[hi], frac);
  g_f0up[i] = __fadd_rn(a, b);
}

// pair-sum levels 1..10 (levels 1-2 in registers; identical __fadd_rn tree)
__global__ __launch_bounds__(256) void k_scan_lo() {
  __shared__ float s[256];
  int b = blockIdx.x, t = threadIdx.x;
  float4 x = ((const float4*)g_f0up)[b * 256 + t];
  float a0 = __fadd_rn(x.x, x.y);
  float a1 = __fadd_rn(x.z, x.w);
  float c  = __fadd_rn(a0, a1);
  ((float2*)(g_lv + LVOFF(1)))[b * 256 + t] = make_float2(a0, a1);
  g_lv[LVOFF(2) + b * 256 + t] = c;
  s[t] = c;
  __syncthreads();
  int n = 128;
  #pragma unroll
  for (int l = 3; l <= 10; l++) {
    float v = 0.0f;
    if (t < n) v = __fadd_rn(s[2 * t], s[2 * t + 1]);
    __syncthreads();
    if (t < n) { s[t] = v; g_lv[LVOFF(l) + b * n + t] = v; }
    __syncthreads();
    n >>= 1;
  }
}

// pair-sum levels 11..22, single block
__global__ __launch_bounds__(1024) void k_scan_hi() {
  __shared__ float s[4096];
  int t = threadIdx.x;
  #pragma unroll
  for (int q = 0; q < 4; q++) s[t + q * 1024] = g_lv[LVOFF(10) + t + q * 1024];
  __syncthreads();
  int n = 2048;
  for (int l = 11; l <= 22; l++) {
    float v0 = 0.0f, v1 = 0.0f;
    if (t < n)        v0 = __fadd_rn(s[2 * t], s[2 * t + 1]);
    if (t + 1024 < n) v1 = __fadd_rn(s[2 * (t + 1024)], s[2 * (t + 1024) + 1]);
    __syncthreads();
    if (t < n)        { s[t] = v0;        g_lv[LVOFF(l) + t] = v0; }
    if (t + 1024 < n) { s[t + 1024] = v1; g_lv[LVOFF(l) + t + 1024] = v1; }
    __syncthreads();
    n >>= 1;
  }
}

// cumsum closed form (jax associative_scan): left-fold of dyadic blocks of [0..n]
__device__ __forceinline__ float saw_at(int n) {
  int m = n + 1;
  float acc = 0.0f;
  bool first = true;
  int start = 0;
  #pragma unroll
  for (int l = 22; l >= 0; --l) {
    if (m & (1 << l)) {
      float v = (l == 0) ? g_f0up[start]
                         : g_lv[LVOFF(l) + (start >> l)];
      acc = first ? v : __fadd_rn(acc, v);
      first = false;
      start += (1 << l);
    }
  }
  float phase = __fdiv_rn(acc, 24000.0f);
  return __fsub_rn(phase, floorf(phase));
}

__global__ __launch_bounds__(256) void k_sawimp() {
  __shared__ float ssaw[257];
  int base = blockIdx.x * 256;
  int t = threadIdx.x;
  ssaw[t] = saw_at(base + t);
  if (t == 0) ssaw[256] = saw_at((base + 256) & (NSIG - 1));
  __syncthreads();
  float d = __fdiv_rn(g_f0up[base + t], 24000.0f);
  g_pulse[base + t] = __fadd_rn(__fsub_rn(ssaw[t], ssaw[t + 1]), d);
}

// --------- fused envelope transposes [513][16384] -> [16384][513] (both) --------
__global__ void k_transpose2(const float* __restrict__ in_n,
                             const float* __restrict__ in_p) {
  __shared__ float tile[32][33];
  int t0 = blockIdx.x * 32, k0 = blockIdx.y * 32;
  int x = t0 + threadIdx.x, y = k0 + threadIdx.y;
  int tx = t0 + threadIdx.y, kx = k0 + threadIdx.x;

  if (y < NBIN) tile[threadIdx.y][threadIdx.x] = in_n[(size_t)y * NFR + x];
  __syncthreads();
  if (kx < NBIN) g_envTn[(size_t)tx * NBIN + kx] = tile[threadIdx.x][threadIdx.y];
  __syncthreads();
  if (y < NBIN) tile[threadIdx.y][threadIdx.x] = in_p[(size_t)y * NFR + x];
  __syncthreads();
  if (kx < NBIN) g_envTp[(size_t)tx * NBIN + kx] = tile[threadIdx.x][threadIdx.y];
}

// ------------------------ register FFT building blocks -------------------------
__device__ __forceinline__ float2 cmul(float2 a, float2 b) {
  return make_float2(a.x * b.x - a.y * b.y, a.x * b.y + a.y * b.x);
}

template<bool INV>
__device__ __forceinline__ void dft4(float2& x0, float2& x1, float2& x2, float2& x3) {
  float t0x = x0.x + x2.x, t0y = x0.y + x2.y;
  float t1x = x0.x - x2.x, t1y = x0.y - x2.y;
  float t2x = x1.x + x3.x, t2y = x1.y + x3.y;
  float t3x = x1.x - x3.x, t3y = x1.y - x3.y;
  x0 = make_float2(t0x + t2x, t0y + t2y);
  x2 = make_float2(t0x - t2x, t0y - t2y);
  if (!INV) {
    x1 = make_float2(t1x + t3y, t1y - t3x);
    x3 = make_float2(t1x - t3y, t1y + t3x);
  } else {
    x1 = make_float2(t1x - t3y, t1y + t3x);
    x3 = make_float2(t1x + t3y, t1y - t3x);
  }
}

template<bool INV>
__device__ __forceinline__ void dft8(float2 c[8]) {
  const float R2 = 0.70710678118654752f;
  float2 e0 = c[0], e1 = c[2], e2 = c[4], e3 = c[6];
  float2 o0 = c[1], o1 = c[3], o2 = c[5], o3 = c[7];
  dft4<INV>(e0, e1, e2, e3);
  dft4<INV>(o0, o1, o2, o3);
  float2 T1, T2, T3;
  if (!INV) {
    T1 = make_float2(R2 * (o1.x + o1.y), R2 * (o1.y - o1.x));
    T2 = make_float2(o2.y, -o2.x);
    T3 = make_float2(R2 * (o3.y - o3.x), R2 * (-o3.x - o3.y));
  } else {
    T1 = make_float2(R2 * (o1.x - o1.y), R2 * (o1.y + o1.x));
    T2 = make_float2(-o2.y, o2.x);
    T3 = make_float2(R2 * (-o3.y - o3.x), R2 * (o3.x - o3.y));
  }
  c[0] = make_float2(e0.x + o0.x, e0.y + o0.y);
  c[4] = make_float2(e0.x - o0.x, e0.y - o0.y);
  c[1] = make_float2(e1.x + T1.x, e1.y + T1.y);
  c[5] = make_float2(e1.x - T1.x, e1.y - T1.y);
  c[2] = make_float2(e2.x + T2.x, e2.y + T2.y);
  c[6] = make_float2(e2.x - T2.x, e2.y - T2.y);
  c[3] = make_float2(e3.x + T3.x, e3.y + T3.y);
  c[7] = make_float2(e3.x - T3.x, e3.y - T3.y);
}

template<bool INV>
__device__ __forceinline__ void dft16(float2 c[16]) {
  const float C1 = 0.92387953251128676f;
  const float S1 = 0.38268343236508977f;
  const float R2 = 0.70710678118654752f;
  const float SG = INV ? -1.0f : 1.0f;
  float2 e[8], o[8];
  #pragma unroll
  for (int q = 0; q < 8; q++) { e[q] = c[2 * q]; o[q] = c[2 * q + 1]; }
  dft8<INV>(e);
  dft8<INV>(o);
  const float2 w[8] = {
    make_float2(1.0f, 0.0f),   make_float2(C1, -SG * S1),
    make_float2(R2, -SG * R2), make_float2(S1, -SG * C1),
    make_float2(0.0f, -SG),    make_float2(-S1, -SG * C1),
    make_float2(-R2, -SG * R2), make_float2(-C1, -SG * S1)};
  #pragma unroll
  for (int r = 0; r < 8; r++) {
    float2 T = cmul(o[r], w[r]);
    c[r]     = make_float2(e[r].x + T.x, e[r].y + T.y);
    c[r + 8] = make_float2(e[r].x - T.x, e[r].y - T.y);
  }
}

__device__ __forceinline__ int SW(int i) { return i + (i >> 4); }
#define WSN 1088

// 1024-pt FFT, 128 threads/group. Input in A (caller synced), output in B.
// One __ldg per stage; twiddle powers via depth-3 product tree.
template<bool INV>
__device__ __forceinline__ void fftg(float2* A, float2* B, int t) {
  { // stage 1: radix-8, m=1, j=t
    float2 c[8];
    #pragma unroll
    for (int q = 0; q < 8; q++) c[q] = A[SW(t + 128 * q)];
    dft8<INV>(c);
    float2 w0 = __ldg(&g_tw[t]);
    float2 w1 = make_float2(w0.x, INV ? -w0.y : w0.y);
    float2 w2 = cmul(w1, w1);
    float2 w3 = cmul(w1, w2);
    float2 w4 = cmul(w2, w2);
    float2 w5 = cmul(w2, w3);
    float2 w6 = cmul(w3, w3);
    float2 w7 = cmul(w3, w4);
    c[1] = cmul(c[1], w1);
    c[2] = cmul(c[2], w2);
    c[3] = cmul(c[3], w3);
    c[4] = cmul(c[4], w4);
    c[5] = cmul(c[5], w5);
    c[6] = cmul(c[6], w6);
    c[7] = cmul(c[7], w7);
    #pragma unroll
    for (int r = 0; r < 8; r++) B[SW(8 * t + r)] = c[r];
  }
  __syncthreads();
  { // stage 2: radix-8, m=8, j=t>>3
    float2 c[8];
    #pragma unroll
    for (int q = 0; q < 8; q++) c[q] = B[SW(t + 128 * q)];
    dft8<INV>(c);
    int j = t >> 3, k = t & 7;
    float2 w0 = __ldg(&g_tw[8 * j]);
    float2 w1 = make_float2(w0.x, INV ? -w0.y : w0.y);
    float2 w2 = cmul(w1, w1);
    float2 w3 = cmul(w1, w2);
    float2 w4 = cmul(w2, w2);
    float2 w5 = cmul(w2, w3);
    float2 w6 = cmul(w3, w3);
    float2 w7 = cmul(w3, w4);
    c[1] = cmul(c[1], w1);
    c[2] = cmul(c[2], w2);
    c[3] = cmul(c[3], w3);
    c[4] = cmul(c[4], w4);
    c[5] = cmul(c[5], w5);
    c[6] = cmul(c[6], w6);
    c[7] = cmul(c[7], w7);
    int o = k + 64 * j;
    #pragma unroll
    for (int r = 0; r < 8; r++) A[SW(o + 8 * r)] = c[r];
  }
  __syncthreads();
  if (t < 64) { // stage 3: radix-16, m=64, j=0 -> no twiddles
    float2 c[16];
    #pragma unroll
    for (int q = 0; q < 16; q++) c[q] = A[SW(t + 64 * q)];
    dft16<INV>(c);
    #pragma unroll
    for (int r = 0; r < 16; r++) B[SW(t + 64 * r)] = c[r];
  }
  __syncthreads();
}

// ------------------------------ per-4-frame mega-kernel -------------------------
// Block: frames 4b..4b+3; group g owns pair (4b+2g, 4b+2g+1).
// Min-phase via Hilbert trick: C[k] = v[k] + i*h[k], v = loaded log-env (registers),
// h from packed FFT of the odd cepstrum part.
__global__ __launch_bounds__(256) void k_frames(const float* __restrict__ noise) {
  __shared__ __align__(16) float2 ws[2][2][WSN];

  int tid = threadIdx.x;
  int g  = tid >> 7;
  int tt = tid & 127;
  int f0 = 4 * blockIdx.x + 2 * g;
  int f1 = f0 + 1;
  float2* WA = ws[g][0];
  float2* WB = ws[g][1];

  // ---- phase 1: packed min-phase input (log-env of f0 + i*f1, symmetric) ----
  float v0r[5], v1r[5];
  #pragma unroll
  for (int q = 0; q < 8; q++) {
    int n = tt + 128 * q;
    int k = (n <= 512) ? n : 1024 - n;
    float a = g_envTp[(size_t)f0 * NBIN + k];
    float b = g_envTp[(size_t)f1 * NBIN + k];
    WA[SW(n)] = make_float2(a, b);
    if (q < 5) { v0r[q] = a; v1r[q] = b; }
  }
  __syncthreads();
  fftg<true>(WA, WB, tt);          // cep0*1024 in Re, cep1*1024 in Im

  // ---- phase 2: odd part of fold ----
  #pragma unroll
  for (int q = 0; q < 8; q++) {
    int n = tt + 128 * q;
    float s = (n == 0 || n == 512) ? 0.0f
            : (n < 512 ? (1.0f / 1024.0f) : (-1.0f / 1024.0f));
    float2 v = WB[SW(n)];
    WA[SW(n)] = make_float2(v.x * s, v.y * s);
  }
  __syncthreads();
  fftg<false>(WA, WB, tt);         // U[k] = -h1[k] + i*h0[k]

  // ---- phase 3: MP = exp(v)*(cos h + i sin h), registers only ----
  float2 MP0[5], MP1[5];
  #pragma unroll
  for (int q = 0; q < 5; q++) {
    int k = tt + 128 * q;
    if (k <= 512) {
      float2 U = WB[SW(k)];
      float h0 = U.y, h1 = -U.x;
      float sn, cs;
      float m0 = __expf(v0r[q]);
      __sincosf(h0, &sn, &cs);
      MP0[q] = make_float2(m0 * cs, m0 * sn);
      float m1 = __expf(v1r[q]);
      __sincosf(h1, &sn, &cs);
      MP1[q] = make_float2(m1 * cs, m1 * sn);
    }
  }

  // ---- phase 4: analysis FFT frame f0 (noise + i*pulse) ----
  #pragma unroll
  for (int q = 0; q < 8; q++) {
    int n = tt + 128 * q;
    int gi = f0 * 256 - 256 + n;
    if (gi < 0) gi = -gi;
    else if (gi >= NSIG) gi = 2 * NSIG - 2 - gi;
    float w = g_w[n];
    WA[SW(n)] = make_float2(noise[gi] * w, g_pulse[gi] * w);
  }
  __syncthreads();
  fftg<false>(WA, WB, tt);

  float2 S0[5];
  #pragma unroll
  for (int q = 0; q < 5; q++) {
    int k = tt + 128 * q;
    if (k <= 512) {
      float2 z1 = WB[SW(k)];
      float2 z2 = WB[SW((1024 - k) & 1023)];
      float en = __expf(g_envTn[(size_t)f0 * NBIN + k]);
      float2 N = make_float2(0.5f * (z1.x + z2.x) * en, 0.5f * (z1.y - z2.y) * en);
      float2 P = make_float2(0.5f * (z1.y + z2.y),      0.5f * (z2.x - z1.x));
      float2 PM = cmul(P, MP0[q]);
      S0[q] = make_float2(N.x + PM.x, N.y + PM.y);
    }
  }

  // ---- phase 5: analysis FFT frame f1, combine, packed synth spectrum ----
  #pragma unroll
  for (int q = 0; q < 8; q++) {
    int n = tt + 128 * q;
    int gi = f1 * 256 - 256 + n;
    if (gi < 0) gi = -gi;
    else if (gi >= NSIG) gi = 2 * NSIG - 2 - gi;
    float w = g_w[n];
    WA[SW(n)] = make_float2(noise[gi] * w, g_pulse[gi] * w);
  }
  __syncthreads();
  fftg<false>(WA, WB, tt);

  #pragma unroll
  for (int q = 0; q < 5; q++) {
    int k = tt + 128 * q;
    if (k <= 512) {
      float2 z1 = WB[SW(k)];
      float2 z2 = WB[SW((1024 - k) & 1023)];
      float en = __expf(g_envTn[(size_t)f1 * NBIN + k]);
      float2 N = make_float2(0.5f * (z1.x + z2.x) * en, 0.5f * (z1.y - z2.y) * en);
      float2 P = make_float2(0.5f * (z1.y + z2.y),      0.5f * (z2.x - z1.x));
      float2 PM = cmul(P, MP1[q]);
      float2 s1 = make_float2(N.x + PM.x, N.y + PM.y);
      float2 s0 = S0[q];
      if (k == 0 || k == 512) { s0.y = 0.0f; s1.y = 0.0f; }   // irfft drops these
      WA[SW(k)] = make_float2(s0.x - s1.y, s0.y + s1.x);
      if (k > 0 && k < 512)
        WA[SW(1024 - k)] = make_float2(s0.x + s1.y, s1.x - s0.y);
    }
  }
  __syncthreads();

  // ---- phase 6: packed synthesis iFFT, window, store both frames ----
  fftg<true>(WA, WB, tt);

  #pragma unroll
  for (int q = 0; q < 8; q++) {
    int n = tt + 128 * q;
    float wsc = (1.0f / 1024.0f) * g_w[n];
    float2 v = WB[SW(n)];
    g_frames[(size_t)f0 * 1024 + n] = v.x * wsc;
    g_frames[(size_t)f1 * 1024 + n] = v.y * wsc;
  }
}

// ----------------------------- overlap-add + wsq -------------------------------
__global__ void k_ola(float* __restrict__ out) {
  int i = blockIdx.x * blockDim.x + threadIdx.x;
  if (i >= OUTLEN) return;
  int p = i + 512;
  if (i >= 256 && i < OUTLEN - 256) {          // interior: exactly 4 full frames
    int jhi = p >> 8;
    int n0 = p & 255;
    const float* base = g_frames + (size_t)(jhi - 3) * 1024;
    float acc = base[n0 + 768];
    acc += base[1024 + n0 + 512];
    acc += base[2048 + n0 + 256];
    acc += base[3072 + n0];
    out[i] = acc * g_wsqinv[n0];
  } else {
    int jhi = p >> 8;
    int jlo = jhi - 3;
    if (jlo < 0) jlo = 0;
    if (jhi > NFR - 1) jhi = NFR - 1;
    float acc = 0.0f, wsq = 0.0f;
    for (int j = jlo; j <= jhi; j++) {
      int n = p - (j << 8);
      acc += g_frames[(size_t)j * 1024 + n];
      float w = g_w[n];
      wsq += w * w;
    }
    out[i] = acc / fmaxf(wsq, 1e-11f);
  }
}

// --------------------------------- launcher ------------------------------------
extern "C" void kernel_launch(void* const* d_in, const int* in_sizes, int n_in,
                              void* d_out, int out_size) {
  const float* log_f0  = (const float*)d_in[0];
  const float* env_noi = (const float*)d_in[1];
  const float* env_per = (const float*)d_in[2];
  const float* noise   = (const float*)d_in[3];
  float* out = (float*)d_out;

  k_init<<<1, 1024>>>();
  k_exp<<<NFR / 256, 256>>>(log_f0);
  k_interp<<<NSIG / 256, 256>>>();
  k_scan_lo<<<NSIG / 1024, 256>>>();
  k_scan_hi<<<1, 1024>>>();
  k_sawimp<<<NSIG / 256, 256>>>();
  dim3 tb(32, 32);
  dim3 tg(NFR / 32, (NBIN + 31) / 32);
  k_transpose2<<<tg, tb>>>(env_noi, env_per);
  k_frames<<<NFR / 4, 256>>>(noise);
  k_ola<<<(OUTLEN + 255) / 256, 256>>>(out);
}

// round 11
// speedup vs baseline: 1.4092x; 1.1090x over previous
#include <cuda_runtime.h>
#include <math.h>

#define NSIG   (1 << 22)              // 4194304 = HOP * N_FRAMES
#define NFR    16384
#define NBIN   513
#define HOPSZ  256
#define OUTLEN ((NFR - 1) * HOPSZ)    // 4194048
#define LVOFF(l) ((1 << 22) - (1 << (23 - (l))))

// ------------------------- device scratch (static per rules) -------------------
__device__ float  g_f0[NFR];
__device__ float  g_f0up[NSIG];
__device__ float  g_lv[NSIG];                    // pair-sum levels 1..22 packed
__device__ float  g_pulse[NSIG];
__device__ float  g_envTn[(size_t)NFR * NBIN];   // transposed log-envelopes [t][k]
__device__ float  g_envTp[(size_t)NFR * NBIN];
__device__ float  g_frames[(size_t)NFR * 1024];  // windowed synthesis frames
__device__ float2 g_tw[256];                     // exp(-2*pi*i*t/1024), t<256
__device__ float  g_w[1024];                     // hann window
__device__ float  g_wsqinv[256];                 // 1/sum_k w^2(n0+256k), interior

// ------------------------------- init tables -----------------------------------
__global__ void k_init() {
  int tid = threadIdx.x;                          // <<<1,1024>>>
  if (tid < 256) {
    double ang = -2.0 * 3.14159265358979323846 * (double)tid / 1024.0;
    g_tw[tid] = make_float2((float)cos(ang), (float)sin(ang));
  }
  g_w[tid] = 0.5f * (1.0f - cosf((float)tid * (6.28318530717958647692f / 1024.0f)));
  __syncthreads();
  if (tid < 256) {
    float w3 = g_w[tid + 768], w2 = g_w[tid + 512], w1 = g_w[tid + 256], w0 = g_w[tid];
    float a = w3 * w3;
    a += w2 * w2;
    a += w1 * w1;
    a += w0 * w0;
    g_wsqinv[tid] = 1.0f / fmaxf(a, 1e-11f);
  }
}

// --------------------- impulse train (bit-replicates JAX) ----------------------
__global__ void k_exp(const float* __restrict__ log_f0) {
  int i = blockIdx.x * blockDim.x + threadIdx.x;
  if (i < NFR) g_f0[i] = expf(log_f0[i]);
}

__global__ void k_interp() {
  int i = blockIdx.x * blockDim.x + threadIdx.x;
  float fi  = (float)i;
  float pos = __fsub_rn(__fdiv_rn(__fadd_rn(fi, 0.5f), 256.0f), 0.5f);
  pos = fminf(fmaxf(pos, 0.0f), 16383.0f);
  float flo = floorf(pos);
  int lo = (int)flo;
  int hi = lo + 1; if (hi > 16383) hi = 16383;
  float frac = __fsub_rn(pos, flo);
  float a = __fmul_rn(g_f0[lo], __fsub_rn(1.0f, frac));
  float b = __fmul_rn(g_f0[hi], frac);
  g_f0up[i] = __fadd_rn(a, b);
}

// pair-sum levels 1..10 (levels 1-2 in registers; identical __fadd_rn tree)
__global__ __launch_bounds__(256) void k_scan_lo() {
  __shared__ float s[256];
  int b = blockIdx.x, t = threadIdx.x;
  float4 x = ((const float4*)g_f0up)[b * 256 + t];
  float a0 = __fadd_rn(x.x, x.y);
  float a1 = __fadd_rn(x.z, x.w);
  float c  = __fadd_rn(a0, a1);
  ((float2*)(g_lv + LVOFF(1)))[b * 256 + t] = make_float2(a0, a1);
  g_lv[LVOFF(2) + b * 256 + t] = c;
  s[t] = c;
  __syncthreads();
  int n = 128;
  #pragma unroll
  for (int l = 3; l <= 10; l++) {
    float v = 0.0f;
    if (t < n) v = __fadd_rn(s[2 * t], s[2 * t + 1]);
    __syncthreads();
    if (t < n) { s[t] = v; g_lv[LVOFF(l) + b * n + t] = v; }
    __syncthreads();
    n >>= 1;
  }
}

// pair-sum levels 11..22, single block
__global__ __launch_bounds__(1024) void k_scan_hi() {
  __shared__ float s[4096];
  int t = threadIdx.x;
  #pragma unroll
  for (int q = 0; q < 4; q++) s[t + q * 1024] = g_lv[LVOFF(10) + t + q * 1024];
  __syncthreads();
  int n = 2048;
  for (int l = 11; l <= 22; l++) {
    float v0 = 0.0f, v1 = 0.0f;
    if (t < n)        v0 = __fadd_rn(s[2 * t], s[2 * t + 1]);
    if (t + 1024 < n) v1 = __fadd_rn(s[2 * (t + 1024)], s[2 * (t + 1024) + 1]);
    __syncthreads();
    if (t < n)        { s[t] = v0;        g_lv[LVOFF(l) + t] = v0; }
    if (t + 1024 < n) { s[t + 1024] = v1; g_lv[LVOFF(l) + t + 1024] = v1; }
    __syncthreads();
    n >>= 1;
  }
}

// cumsum closed form (jax associative_scan): left-fold of dyadic blocks of [0..n]
__device__ __forceinline__ float saw_at(int n) {
  int m = n + 1;
  float acc = 0.0f;
  bool first = true;
  int start = 0;
  #pragma unroll
  for (int l = 22; l >= 0; --l) {
    if (m & (1 << l)) {
      float v = (l == 0) ? g_f0up[start]
                         : g_lv[LVOFF(l) + (start >> l)];
      acc = first ? v : __fadd_rn(acc, v);
      first = false;
      start += (1 << l);
    }
  }
  float phase = __fdiv_rn(acc, 24000.0f);
  return __fsub_rn(phase, floorf(phase));
}

__global__ __launch_bounds__(256) void k_sawimp() {
  __shared__ float ssaw[257];
  int base = blockIdx.x * 256;
  int t = threadIdx.x;
  ssaw[t] = saw_at(base + t);
  if (t == 0) ssaw[256] = saw_at((base + 256) & (NSIG - 1));
  __syncthreads();
  float d = __fdiv_rn(g_f0up[base + t], 24000.0f);
  g_pulse[base + t] = __fadd_rn(__fsub_rn(ssaw[t], ssaw[t + 1]), d);
}

// --------- fused envelope transposes [513][16384] -> [16384][513] (both) --------
__global__ void k_transpose2(const float* __restrict__ in_n,
                             const float* __restrict__ in_p) {
  __shared__ float tile[32][33];
  int t0 = blockIdx.x * 32, k0 = blockIdx.y * 32;
  int x = t0 + threadIdx.x, y = k0 + threadIdx.y;
  int tx = t0 + threadIdx.y, kx = k0 + threadIdx.x;

  if (y < NBIN) tile[threadIdx.y][threadIdx.x] = in_n[(size_t)y * NFR + x];
  __syncthreads();
  if (kx < NBIN) g_envTn[(size_t)tx * NBIN + kx] = tile[threadIdx.x][threadIdx.y];
  __syncthreads();
  if (y < NBIN) tile[threadIdx.y][threadIdx.x] = in_p[(size_t)y * NFR + x];
  __syncthreads();
  if (kx < NBIN) g_envTp[(size_t)tx * NBIN + kx] = tile[threadIdx.x][threadIdx.y];
}

// ------------------------ register FFT building blocks -------------------------
__device__ __forceinline__ float2 cmul(float2 a, float2 b) {
  return make_float2(a.x * b.x - a.y * b.y, a.x * b.y + a.y * b.x);
}

template<bool INV>
__device__ __forceinline__ void dft4(float2& x0, float2& x1, float2& x2, float2& x3) {
  float t0x = x0.x + x2.x, t0y = x0.y + x2.y;
  float t1x = x0.x - x2.x, t1y = x0.y - x2.y;
  float t2x = x1.x + x3.x, t2y = x1.y + x3.y;
  float t3x = x1.x - x3.x, t3y = x1.y - x3.y;
  x0 = make_float2(t0x + t2x, t0y + t2y);
  x2 = make_float2(t0x - t2x, t0y - t2y);
  if (!INV) {
    x1 = make_float2(t1x + t3y, t1y - t3x);
    x3 = make_float2(t1x - t3y, t1y + t3x);
  } else {
    x1 = make_float2(t1x - t3y, t1y + t3x);
    x3 = make_float2(t1x + t3y, t1y - t3x);
  }
}

template<bool INV>
__device__ __forceinline__ void dft8(float2 c[8]) {
  const float R2 = 0.70710678118654752f;
  float2 e0 = c[0], e1 = c[2], e2 = c[4], e3 = c[6];
  float2 o0 = c[1], o1 = c[3], o2 = c[5], o3 = c[7];
  dft4<INV>(e0, e1, e2, e3);
  dft4<INV>(o0, o1, o2, o3);
  float2 T1, T2, T3;
  if (!INV) {
    T1 = make_float2(R2 * (o1.x + o1.y), R2 * (o1.y - o1.x));
    T2 = make_float2(o2.y, -o2.x);
    T3 = make_float2(R2 * (o3.y - o3.x), R2 * (-o3.x - o3.y));
  } else {
    T1 = make_float2(R2 * (o1.x - o1.y), R2 * (o1.y + o1.x));
    T2 = make_float2(-o2.y, o2.x);
    T3 = make_float2(R2 * (-o3.y - o3.x), R2 * (o3.x - o3.y));
  }
  c[0] = make_float2(e0.x + o0.x, e0.y + o0.y);
  c[4] = make_float2(e0.x - o0.x, e0.y - o0.y);
  c[1] = make_float2(e1.x + T1.x, e1.y + T1.y);
  c[5] = make_float2(e1.x - T1.x, e1.y - T1.y);
  c[2] = make_float2(e2.x + T2.x, e2.y + T2.y);
  c[6] = make_float2(e2.x - T2.x, e2.y - T2.y);
  c[3] = make_float2(e3.x + T3.x, e3.y + T3.y);
  c[7] = make_float2(e3.x - T3.x, e3.y - T3.y);
}

template<bool INV>
__device__ __forceinline__ void dft16(float2 c[16]) {
  const float C1 = 0.92387953251128676f;
  const float S1 = 0.38268343236508977f;
  const float R2 = 0.70710678118654752f;
  const float SG = INV ? -1.0f : 1.0f;
  float2 e[8], o[8];
  #pragma unroll
  for (int q = 0; q < 8; q++) { e[q] = c[2 * q]; o[q] = c[2 * q + 1]; }
  dft8<INV>(e);
  dft8<INV>(o);
  const float2 w[8] = {
    make_float2(1.0f, 0.0f),   make_float2(C1, -SG * S1),
    make_float2(R2, -SG * R2), make_float2(S1, -SG * C1),
    make_float2(0.0f, -SG),    make_float2(-S1, -SG * C1),
    make_float2(-R2, -SG * R2), make_float2(-C1, -SG * S1)};
  #pragma unroll
  for (int r = 0; r < 8; r++) {
    float2 T = cmul(o[r], w[r]);
    c[r]     = make_float2(e[r].x + T.x, e[r].y + T.y);
    c[r + 8] = make_float2(e[r].x - T.x, e[r].y - T.y);
  }
}

__device__ __forceinline__ int SW(int i) { return i + (i >> 4); }
#define WSN 1088

// 1024-pt FFT, 128 threads. Stage 1 inputs come from a loader functor (registers,
// no smem staging). stage1 -> X, stage2 -> Y, stage3 -> X. Output in X.
// The loader may read Y elementwise (consumed entirely by stage 1).
template<bool INV, class LD>
__device__ __forceinline__ void fftg2(float2* X, float2* Y, int t, LD ld) {
  { // stage 1: radix-8, m=1, j=t
    float2 c[8];
    #pragma unroll
    for (int q = 0; q < 8; q++) c[q] = ld(t + 128 * q, q);
    dft8<INV>(c);
    float2 w0 = __ldg(&g_tw[t]);
    float2 w1 = make_float2(w0.x, INV ? -w0.y : w0.y);
    float2 w2 = cmul(w1, w1);
    float2 w3 = cmul(w1, w2);
    float2 w4 = cmul(w2, w2);
    float2 w5 = cmul(w2, w3);
    float2 w6 = cmul(w3, w3);
    float2 w7 = cmul(w3, w4);
    c[1] = cmul(c[1], w1);
    c[2] = cmul(c[2], w2);
    c[3] = cmul(c[3], w3);
    c[4] = cmul(c[4], w4);
    c[5] = cmul(c[5], w5);
    c[6] = cmul(c[6], w6);
    c[7] = cmul(c[7], w7);
    #pragma unroll
    for (int r = 0; r < 8; r++) X[SW(8 * t + r)] = c[r];
  }
  __syncthreads();
  { // stage 2: radix-8, m=8
    float2 c[8];
    #pragma unroll
    for (int q = 0; q < 8; q++) c[q] = X[SW(t + 128 * q)];
    dft8<INV>(c);
    int j = t >> 3, k = t & 7;
    float2 w0 = __ldg(&g_tw[8 * j]);
    float2 w1 = make_float2(w0.x, INV ? -w0.y : w0.y);
    float2 w2 = cmul(w1, w1);
    float2 w3 = cmul(w1, w2);
    float2 w4 = cmul(w2, w2);
    float2 w5 = cmul(w2, w3);
    float2 w6 = cmul(w3, w3);
    float2 w7 = cmul(w3, w4);
    c[1] = cmul(c[1], w1);
    c[2] = cmul(c[2], w2);
    c[3] = cmul(c[3], w3);
    c[4] = cmul(c[4], w4);
    c[5] = cmul(c[5], w5);
    c[6] = cmul(c[6], w6);
    c[7] = cmul(c[7], w7);
    int o = k + 64 * j;
    #pragma unroll
    for (int r = 0; r < 8; r++) Y[SW(o + 8 * r)] = c[r];
  }
  __syncthreads();
  if (t < 64) { // stage 3: radix-16, m=64, j=0 -> no twiddles
    float2 c[16];
    #pragma unroll
    for (int q = 0; q < 16; q++) c[q] = Y[SW(t + 64 * q)];
    dft16<INV>(c);
    #pragma unroll
    for (int r = 0; r < 16; r++) X[SW(t + 64 * r)] = c[r];
  }
  __syncthreads();
}

// ------------------------------ per-frame-pair kernel ---------------------------
// 128 threads, one pair (f0 = 2b, f1 = 2b+1). 5 FFTs, inputs fused into stage 1.
__global__ __launch_bounds__(128) void k_frames(const float* __restrict__ noise) {
  __shared__ __align__(16) float2 WA[WSN];
  __shared__ __align__(16) float2 WB[WSN];

  int tt = threadIdx.x;                   // 0..127
  int f0 = 2 * blockIdx.x;
  int f1 = f0 + 1;
  const float* ep0 = g_envTp + (size_t)f0 * NBIN;
  const float* ep1 = g_envTp + (size_t)f1 * NBIN;

  // ---- FFT1: packed min-phase iDFT of symmetric log-envelopes (direct load) ----
  float v0r[5], v1r[5];
  fftg2<true>(WA, WB, tt, [&](int n, int q) {
    int k = (n <= 512) ? n : 1024 - n;
    float a = ep0[k];
    float b = ep1[k];
    if (q < 5) { v0r[q] = a; v1r[q] = b; }
    return make_float2(a, b);
  });                                      // out: WA = cep*1024 (packed)

  // ---- FFT2: forward FFT of odd cepstrum part (fold fused into loader) ----
  fftg2<false>(WB, WA, tt, [&](int n, int q) {
    float s = (n == 0 || n == 512) ? 0.0f
            : (n < 512 ? (1.0f / 1024.0f) : (-1.0f / 1024.0f));
    float2 v = WA[SW(n)];
    return make_float2(v.x * s, v.y * s);
  });                                      // out: WB, U[k] = -h1[k] + i*h0[k]

  // ---- min-phase exp -> registers ----
  float2 MP0[5], MP1[5];
  #pragma unroll
  for (int q = 0; q < 5; q++) {
    int k = tt + 128 * q;
    if (k <= 512) {
      float2 U = WB[SW(k)];
      float sn, cs;
      float m0 = __expf(v0r[q]);
      __sincosf(U.y, &sn, &cs);
      MP0[q] = make_float2(m0 * cs, m0 * sn);
      float m1 = __expf(v1r[q]);
      __sincosf(-U.x, &sn, &cs);
      MP1[q] = make_float2(m1 * cs, m1 * sn);
    }
  }

  // ---- FFT3: analysis of frame f0 (noise + i*pulse, direct load) ----
  fftg2<false>(WA, WB, tt, [&](int n, int q) {
    int gi = f0 * 256 - 256 + n;
    if (gi < 0) gi = -gi;
    else if (gi >= NSIG) gi = 2 * NSIG - 2 - gi;
    float w = g_w[n];
    return make_float2(noise[gi] * w, g_pulse[gi] * w);
  });                                      // out: WA

  float2 S0[5];
  #pragma unroll
  for (int q = 0; q < 5; q++) {
    int k = tt + 128 * q;
    if (k <= 512) {
      float2 z1 = WA[SW(k)];
      float2 z2 = WA[SW((1024 - k) & 1023)];
      float en = __expf(g_envTn[(size_t)f0 * NBIN + k]);
      float2 N = make_float2(0.5f * (z1.x + z2.x) * en, 0.5f * (z1.y - z2.y) * en);
      float2 P = make_float2(0.5f * (z1.y + z2.y),      0.5f * (z2.x - z1.x));
      float2 PM = cmul(P, MP0[q]);
      S0[q] = make_float2(N.x + PM.x, N.y + PM.y);
    }
  }
  // (no sync needed: FFT4 stage 1 writes WB only; its first sync protects WA)

  // ---- FFT4: analysis of frame f1 ----
  fftg2<false>(WB, WA, tt, [&](int n, int q) {
    int gi = f1 * 256 - 256 + n;
    if (gi < 0) gi = -gi;
    else if (gi >= NSIG) gi = 2 * NSIG - 2 - gi;
    float w = g_w[n];
    return make_float2(noise[gi] * w, g_pulse[gi] * w);
  });                                      // out: WB

  // ---- combine + build packed synthesis spectrum into WA ----
  #pragma unroll
  for (int q = 0; q < 5; q++) {
    int k = tt + 128 * q;
    if (k <= 512) {
      float2 z1 = WB[SW(k)];
      float2 z2 = WB[SW((1024 - k) & 1023)];
      float en = __expf(g_envTn[(size_t)f1 * NBIN + k]);
      float2 N = make_float2(0.5f * (z1.x + z2.x) * en, 0.5f * (z1.y - z2.y) * en);
      float2 P = make_float2(0.5f * (z1.y + z2.y),      0.5f * (z2.x - z1.x));
      float2 PM = cmul(P, MP1[q]);
      float2 s1 = make_float2(N.x + PM.x, N.y + PM.y);
      float2 s0 = S0[q];
      if (k == 0 || k == 512) { s0.y = 0.0f; s1.y = 0.0f; }   // irfft drops these
      WA[SW(k)] = make_float2(s0.x - s1.y, s0.y + s1.x);
      if (k > 0 && k < 512)
        WA[SW(1024 - k)] = make_float2(s0.x + s1.y, s1.x - s0.y);
    }
  }
  __syncthreads();

  // ---- FFT5: packed synthesis iFFT (copy loader from WA) ----
  fftg2<true>(WB, WA, tt, [&](int n, int q) {
    return WA[SW(n)];
  });                                      // out: WB

  #pragma unroll
  for (int q = 0; q < 8; q++) {
    int n = tt + 128 * q;
    float wsc = (1.0f / 1024.0f) * g_w[n];
    float2 v = WB[SW(n)];
    g_frames[(size_t)f0 * 1024 + n] = v.x * wsc;
    g_frames[(size_t)f1 * 1024 + n] = v.y * wsc;
  }
}

// ----------------------------- overlap-add + wsq -------------------------------
__global__ void k_ola(float* __restrict__ out) {
  int i = blockIdx.x * blockDim.x + threadIdx.x;
  if (i >= OUTLEN) return;
  int p = i + 512;
  if (i >= 256 && i < OUTLEN - 256) {          // interior: exactly 4 full frames
    int jhi = p >> 8;
    int n0 = p & 255;
    const float* base = g_frames + (size_t)(jhi - 3) * 1024;
    float acc = base[n0 + 768];
    acc += base[1024 + n0 + 512];
    acc += base[2048 + n0 + 256];
    acc += base[3072 + n0];
    out[i] = acc * g_wsqinv[n0];
  } else {
    int jhi = p >> 8;
    int jlo = jhi - 3;
    if (jlo < 0) jlo = 0;
    if (jhi > NFR - 1) jhi = NFR - 1;
    float acc = 0.0f, wsq = 0.0f;
    for (int j = jlo; j <= jhi; j++) {
      int n = p - (j << 8);
      acc += g_frames[(size_t)j * 1024 + n];
      float w = g_w[n];
      wsq += w * w;
    }
    out[i] = acc / fmaxf(wsq, 1e-11f);
  }
}

// --------------------------------- launcher ------------------------------------
extern "C" void kernel_launch(void* const* d_in, const int* in_sizes, int n_in,
                              void* d_out, int out_size) {
  const float* log_f0  = (const float*)d_in[0];
  const float* env_noi = (const float*)d_in[1];
  const float* env_per = (const float*)d_in[2];
  const float* noise   = (const float*)d_in[3];
  float* out = (float*)d_out;

  k_init<<<1, 1024>>>();
  k_exp<<<NFR / 256, 256>>>(log_f0);
  k_interp<<<NSIG / 256, 256>>>();
  k_scan_lo<<<NSIG / 1024, 256>>>();
  k_scan_hi<<<1, 1024>>>();
  k_sawimp<<<NSIG / 256, 256>>>();
  dim3 tb(32, 32);
  dim3 tg(NFR / 32, (NBIN + 31) / 32);
  k_transpose2<<<tg, tb>>>(env_noi, env_per);
  k_frames<<<NFR / 2, 128>>>(noise);
  k_ola<<<(OUTLEN + 255) / 256, 256>>>(out);
}

// round 12
// speedup vs baseline: 1.4429x; 1.0239x over previous
#include <cuda_runtime.h>
#include <math.h>

#define NSIG   (1 << 22)              // 4194304 = HOP * N_FRAMES
#define NFR    16384
#define NBIN   513
#define HOPSZ  256
#define OUTLEN ((NFR - 1) * HOPSZ)    // 4194048
#define LVOFF(l) ((1 << 22) - (1 << (23 - (l))))

// ------------------------- device scratch (static per rules) -------------------
__device__ float  g_f0[NFR];
__device__ float  g_f0up[NSIG];
__device__ float  g_lv[NSIG];                    // pair-sum levels 1..22 packed
__device__ float  g_pulse[NSIG];
__device__ float  g_envTn[(size_t)NFR * NBIN];   // transposed log-envelopes [t][k]
__device__ float  g_envTp[(size_t)NFR * NBIN];
__device__ float  g_frames[(size_t)NFR * 1024];  // windowed synthesis frames
__device__ float2 g_tw[256];                     // exp(-2*pi*i*t/1024), t<256
__device__ float  g_w[1024];                     // hann window
__device__ float  g_wsqinv[256];                 // 1/sum_k w^2(n0+256k), interior

// ------------------------------- init tables -----------------------------------
__global__ void k_init() {
  int tid = threadIdx.x;                          // <<<1,1024>>>
  if (tid < 256) {
    double ang = -2.0 * 3.14159265358979323846 * (double)tid / 1024.0;
    g_tw[tid] = make_float2((float)cos(ang), (float)sin(ang));
  }
  g_w[tid] = 0.5f * (1.0f - cosf((float)tid * (6.28318530717958647692f / 1024.0f)));
  __syncthreads();
  if (tid < 256) {
    float w3 = g_w[tid + 768], w2 = g_w[tid + 512], w1 = g_w[tid + 256], w0 = g_w[tid];
    float a = w3 * w3;
    a += w2 * w2;
    a += w1 * w1;
    a += w0 * w0;
    g_wsqinv[tid] = 1.0f / fmaxf(a, 1e-11f);
  }
}

// --------------------- impulse train (bit-replicates JAX) ----------------------
__global__ void k_exp(const float* __restrict__ log_f0) {
  int i = blockIdx.x * blockDim.x + threadIdx.x;
  if (i < NFR) g_f0[i] = expf(log_f0[i]);
}

// fused: linear interp (bit-identical per-sample ops) + pair-sum levels 1..10
__global__ __launch_bounds__(256) void k_scan_lo() {
  __shared__ float s[256];
  int b = blockIdx.x, t = threadIdx.x;
  float v[4];
  #pragma unroll
  for (int j = 0; j < 4; j++) {
    int i = b * 1024 + 4 * t + j;
    float fi  = (float)i;
    float pos = __fsub_rn(__fdiv_rn(__fadd_rn(fi, 0.5f), 256.0f), 0.5f);
    pos = fminf(fmaxf(pos, 0.0f), 16383.0f);
    float flo = floorf(pos);
    int lo = (int)flo;
    int hi = lo + 1; if (hi > 16383) hi = 16383;
    float frac = __fsub_rn(pos, flo);
    v[j] = __fadd_rn(__fmul_rn(g_f0[lo], __fsub_rn(1.0f, frac)),
                     __fmul_rn(g_f0[hi], frac));
  }
  ((float4*)g_f0up)[b * 256 + t] = make_float4(v[0], v[1], v[2], v[3]);
  float a0 = __fadd_rn(v[0], v[1]);
  float a1 = __fadd_rn(v[2], v[3]);
  float c  = __fadd_rn(a0, a1);
  ((float2*)(g_lv + LVOFF(1)))[b * 256 + t] = make_float2(a0, a1);
  g_lv[LVOFF(2) + b * 256 + t] = c;
  s[t] = c;
  __syncthreads();
  int n = 128;
  #pragma unroll
  for (int l = 3; l <= 10; l++) {
    float vv = 0.0f;
    if (t < n) vv = __fadd_rn(s[2 * t], s[2 * t + 1]);
    __syncthreads();
    if (t < n) { s[t] = vv; g_lv[LVOFF(l) + b * n + t] = vv; }
    __syncthreads();
    n >>= 1;
  }
}

// pair-sum levels 11..22, single block
__global__ __launch_bounds__(1024) void k_scan_hi() {
  __shared__ float s[4096];
  int t = threadIdx.x;
  #pragma unroll
  for (int q = 0; q < 4; q++) s[t + q * 1024] = g_lv[LVOFF(10) + t + q * 1024];
  __syncthreads();
  int n = 2048;
  for (int l = 11; l <= 22; l++) {
    float v0 = 0.0f, v1 = 0.0f;
    if (t < n)        v0 = __fadd_rn(s[2 * t], s[2 * t + 1]);
    if (t + 1024 < n) v1 = __fadd_rn(s[2 * (t + 1024)], s[2 * (t + 1024) + 1]);
    __syncthreads();
    if (t < n)        { s[t] = v0;        g_lv[LVOFF(l) + t] = v0; }
    if (t + 1024 < n) { s[t + 1024] = v1; g_lv[LVOFF(l) + t + 1024] = v1; }
    __syncthreads();
    n >>= 1;
  }
}

// cumsum closed form (jax associative_scan): left-fold of dyadic blocks of [0..n]
__device__ __forceinline__ float saw_at(int n) {
  int m = n + 1;
  float acc = 0.0f;
  bool first = true;
  int start = 0;
  #pragma unroll
  for (int l = 22; l >= 0; --l) {
    if (m & (1 << l)) {
      float v = (l == 0) ? g_f0up[start]
                         : g_lv[LVOFF(l) + (start >> l)];
      acc = first ? v : __fadd_rn(acc, v);
      first = false;
      start += (1 << l);
    }
  }
  float phase = __fdiv_rn(acc, 24000.0f);
  return __fsub_rn(phase, floorf(phase));
}

__global__ __launch_bounds__(256) void k_sawimp() {
  __shared__ float ssaw[257];
  int base = blockIdx.x * 256;
  int t = threadIdx.x;
  ssaw[t] = saw_at(base + t);
  if (t == 0) ssaw[256] = saw_at((base + 256) & (NSIG - 1));
  __syncthreads();
  float d = __fdiv_rn(g_f0up[base + t], 24000.0f);
  g_pulse[base + t] = __fadd_rn(__fsub_rn(ssaw[t], ssaw[t + 1]), d);
}

// --------- fused envelope transposes [513][16384] -> [16384][513] (both) --------
__global__ void k_transpose2(const float* __restrict__ in_n,
                             const float* __restrict__ in_p) {
  __shared__ float tile[32][33];
  int t0 = blockIdx.x * 32, k0 = blockIdx.y * 32;
  int x = t0 + threadIdx.x, y = k0 + threadIdx.y;
  int tx = t0 + threadIdx.y, kx = k0 + threadIdx.x;

  if (y < NBIN) tile[threadIdx.y][threadIdx.x] = in_n[(size_t)y * NFR + x];
  __syncthreads();
  if (kx < NBIN) g_envTn[(size_t)tx * NBIN + kx] = tile[threadIdx.x][threadIdx.y];
  __syncthreads();
  if (y < NBIN) tile[threadIdx.y][threadIdx.x] = in_p[(size_t)y * NFR + x];
  __syncthreads();
  if (kx < NBIN) g_envTp[(size_t)tx * NBIN + kx] = tile[threadIdx.x][threadIdx.y];
}

// ------------------------ register FFT building blocks -------------------------
__device__ __forceinline__ float2 cmul(float2 a, float2 b) {
  return make_float2(a.x * b.x - a.y * b.y, a.x * b.y + a.y * b.x);
}

template<bool INV>
__device__ __forceinline__ void dft4(float2& x0, float2& x1, float2& x2, float2& x3) {
  float t0x = x0.x + x2.x, t0y = x0.y + x2.y;
  float t1x = x0.x - x2.x, t1y = x0.y - x2.y;
  float t2x = x1.x + x3.x, t2y = x1.y + x3.y;
  float t3x = x1.x - x3.x, t3y = x1.y - x3.y;
  x0 = make_float2(t0x + t2x, t0y + t2y);
  x2 = make_float2(t0x - t2x, t0y - t2y);
  if (!INV) {
    x1 = make_float2(t1x + t3y, t1y - t3x);
    x3 = make_float2(t1x - t3y, t1y + t3x);
  } else {
    x1 = make_float2(t1x - t3y, t1y + t3x);
    x3 = make_float2(t1x + t3y, t1y - t3x);
  }
}

template<bool INV>
__device__ __forceinline__ void dft8(float2 c[8]) {
  const float R2 = 0.70710678118654752f;
  float2 e0 = c[0], e1 = c[2], e2 = c[4], e3 = c[6];
  float2 o0 = c[1], o1 = c[3], o2 = c[5], o3 = c[7];
  dft4<INV>(e0, e1, e2, e3);
  dft4<INV>(o0, o1, o2, o3);
  float2 T1, T2, T3;
  if (!INV) {
    T1 = make_float2(R2 * (o1.x + o1.y), R2 * (o1.y - o1.x));
    T2 = make_float2(o2.y, -o2.x);
    T3 = make_float2(R2 * (o3.y - o3.x), R2 * (-o3.x - o3.y));
  } else {
    T1 = make_float2(R2 * (o1.x - o1.y), R2 * (o1.y + o1.x));
    T2 = make_float2(-o2.y, o2.x);
    T3 = make_float2(R2 * (-o3.y - o3.x), R2 * (o3.x - o3.y));
  }
  c[0] = make_float2(e0.x + o0.x, e0.y + o0.y);
  c[4] = make_float2(e0.x - o0.x, e0.y - o0.y);
  c[1] = make_float2(e1.x + T1.x, e1.y + T1.y);
  c[5] = make_float2(e1.x - T1.x, e1.y - T1.y);
  c[2] = make_float2(e2.x + T2.x, e2.y + T2.y);
  c[6] = make_float2(e2.x - T2.x, e2.y - T2.y);
  c[3] = make_float2(e3.x + T3.x, e3.y + T3.y);
  c[7] = make_float2(e3.x - T3.x, e3.y - T3.y);
}

template<bool INV>
__device__ __forceinline__ void dft16(float2 c[16]) {
  const float C1 = 0.92387953251128676f;
  const float S1 = 0.38268343236508977f;
  const float R2 = 0.70710678118654752f;
  const float SG = INV ? -1.0f : 1.0f;
  float2 e[8], o[8];
  #pragma unroll
  for (int q = 0; q < 8; q++) { e[q] = c[2 * q]; o[q] = c[2 * q + 1]; }
  dft8<INV>(e);
  dft8<INV>(o);
  const float2 w[8] = {
    make_float2(1.0f, 0.0f),   make_float2(C1, -SG * S1),
    make_float2(R2, -SG * R2), make_float2(S1, -SG * C1),
    make_float2(0.0f, -SG),    make_float2(-S1, -SG * C1),
    make_float2(-R2, -SG * R2), make_float2(-C1, -SG * S1)};
  #pragma unroll
  for (int r = 0; r < 8; r++) {
    float2 T = cmul(o[r], w[r]);
    c[r]     = make_float2(e[r].x + T.x, e[r].y + T.y);
    c[r + 8] = make_float2(e[r].x - T.x, e[r].y - T.y);
  }
}

__device__ __forceinline__ int SW(int i) { return i + (i >> 4); }
#define WSN 1088

// 1024-pt FFT, 128 threads. Stage 1 inputs from loader functor.
// stage1 -> X, stage2 -> Y, stage3 -> X. Loader may read Y elementwise.
template<bool INV, class LD>
__device__ __forceinline__ void fftg2(float2* X, float2* Y, int t, LD ld) {
  { // stage 1: radix-8, m=1, j=t
    float2 c[8];
    #pragma unroll
    for (int q = 0; q < 8; q++) c[q] = ld(t + 128 * q, q);
    dft8<INV>(c);
    float2 w0 = __ldg(&g_tw[t]);
    float2 w1 = make_float2(w0.x, INV ? -w0.y : w0.y);
    float2 w2 = cmul(w1, w1);
    float2 w3 = cmul(w1, w2);
    float2 w4 = cmul(w2, w2);
    float2 w5 = cmul(w2, w3);
    float2 w6 = cmul(w3, w3);
    float2 w7 = cmul(w3, w4);
    c[1] = cmul(c[1], w1);
    c[2] = cmul(c[2], w2);
    c[3] = cmul(c[3], w3);
    c[4] = cmul(c[4], w4);
    c[5] = cmul(c[5], w5);
    c[6] = cmul(c[6], w6);
    c[7] = cmul(c[7], w7);
    #pragma unroll
    for (int r = 0; r < 8; r++) X[SW(8 * t + r)] = c[r];
  }
  __syncthreads();
  { // stage 2: radix-8, m=8
    float2 c[8];
    #pragma unroll
    for (int q = 0; q < 8; q++) c[q] = X[SW(t + 128 * q)];
    dft8<INV>(c);
    int j = t >> 3, k = t & 7;
    float2 w0 = __ldg(&g_tw[8 * j]);
    float2 w1 = make_float2(w0.x, INV ? -w0.y : w0.y);
    float2 w2 = cmul(w1, w1);
    float2 w3 = cmul(w1, w2);
    float2 w4 = cmul(w2, w2);
    float2 w5 = cmul(w2, w3);
    float2 w6 = cmul(w3, w3);
    float2 w7 = cmul(w3, w4);
    c[1] = cmul(c[1], w1);
    c[2] = cmul(c[2], w2);
    c[3] = cmul(c[3], w3);
    c[4] = cmul(c[4], w4);
    c[5] = cmul(c[5], w5);
    c[6] = cmul(c[6], w6);
    c[7] = cmul(c[7], w7);
    int o = k + 64 * j;
    #pragma unroll
    for (int r = 0; r < 8; r++) Y[SW(o + 8 * r)] = c[r];
  }
  __syncthreads();
  if (t < 64) { // stage 3: radix-16, m=64, j=0 -> no twiddles
    float2 c[16];
    #pragma unroll
    for (int q = 0; q < 16; q++) c[q] = Y[SW(t + 64 * q)];
    dft16<INV>(c);
    #pragma unroll
    for (int r = 0; r < 16; r++) X[SW(t + 64 * r)] = c[r];
  }
  __syncthreads();
}

// ------------------------------ per-frame-pair kernel ---------------------------
// 128 threads, one pair (f0 = 2b, f1 = 2b+1). 5 FFTs, inputs fused into stage 1.
// Inter-FFT spectral state lives in per-thread-owned smem (no syncs needed):
//   sS0: MP0 until FFT3 finishes, then S0 in place.  sMP1: MP1.
__global__ __launch_bounds__(128, 7) void k_frames(const float* __restrict__ noise) {
  __shared__ __align__(16) float2 WA[WSN];
  __shared__ __align__(16) float2 WB[WSN];
  __shared__ float2 sS0[NBIN];
  __shared__ float2 sMP1[NBIN];

  int tt = threadIdx.x;                   // 0..127
  int f0 = 2 * blockIdx.x;
  int f1 = f0 + 1;
  const float* ep0 = g_envTp + (size_t)f0 * NBIN;
  const float* ep1 = g_envTp + (size_t)f1 * NBIN;

  // ---- FFT1: packed min-phase iDFT of symmetric log-envelopes (direct load) ----
  fftg2<true>(WA, WB, tt, [&](int n, int q) {
    int k = (n <= 512) ? n : 1024 - n;
    return make_float2(ep0[k], ep1[k]);
  });                                      // out: WA = cep*1024 (packed)

  // ---- FFT2: forward FFT of odd cepstrum part (fold fused into loader) ----
  fftg2<false>(WB, WA, tt, [&](int n, int q) {
    float s = (n == 0 || n == 512) ? 0.0f
            : (n < 512 ? (1.0f / 1024.0f) : (-1.0f / 1024.0f));
    float2 v = WA[SW(n)];
    return make_float2(v.x * s, v.y * s);
  });                                      // out: WB, U[k] = -h1[k] + i*h0[k]

  // ---- min-phase exp -> per-thread smem (MP0 parks in sS0) ----
  #pragma unroll
  for (int q = 0; q < 5; q++) {
    int k = tt + 128 * q;
    if (k <= 512) {
      float2 U = WB[SW(k)];
      float sn, cs;
      float m0 = __expf(ep0[k]);
      __sincosf(U.y, &sn, &cs);
      sS0[k] = make_float2(m0 * cs, m0 * sn);
      float m1 = __expf(ep1[k]);
      __sincosf(-U.x, &sn, &cs);
      sMP1[k] = make_float2(m1 * cs, m1 * sn);
    }
  }

  // ---- FFT3: analysis of frame f0 (noise + i*pulse, direct load) ----
  fftg2<false>(WA, WB, tt, [&](int n, int q) {
    int gi = f0 * 256 - 256 + n;
    if (gi < 0) gi = -gi;
    else if (gi >= NSIG) gi = 2 * NSIG - 2 - gi;
    float w = g_w[n];
    return make_float2(noise[gi] * w, g_pulse[gi] * w);
  });                                      // out: WA

  // S0 = N0 + P0*MP0, stored in place of MP0 (same-thread bins, no sync)
  #pragma unroll
  for (int q = 0; q < 5; q++) {
    int k = tt + 128 * q;
    if (k <= 512) {
      float2 z1 = WA[SW(k)];
      float2 z2 = WA[SW((1024 - k) & 1023)];
      float en = __expf(g_envTn[(size_t)f0 * NBIN + k]);
      float2 N = make_float2(0.5f * (z1.x + z2.x) * en, 0.5f * (z1.y - z2.y) * en);
      float2 P = make_float2(0.5f * (z1.y + z2.y),      0.5f * (z2.x - z1.x));
      float2 PM = cmul(P, sS0[k]);
      sS0[k] = make_float2(N.x + PM.x, N.y + PM.y);
    }
  }
  // (no sync needed: FFT4 stage 1 writes WB only; its first sync protects WA)

  // ---- FFT4: analysis of frame f1 ----
  fftg2<false>(WB, WA, tt, [&](int n, int q) {
    int gi = f1 * 256 - 256 + n;
    if (gi < 0) gi = -gi;
    else if (gi >= NSIG) gi = 2 * NSIG - 2 - gi;
    float w = g_w[n];
    return make_float2(noise[gi] * w, g_pulse[gi] * w);
  });                                      // out: WB

  // ---- combine + build packed synthesis spectrum into WA ----
  #pragma unroll
  for (int q = 0; q < 5; q++) {
    int k = tt + 128 * q;
    if (k <= 512) {
      float2 z1 = WB[SW(k)];
      float2 z2 = WB[SW((1024 - k) & 1023)];
      float en = __expf(g_envTn[(size_t)f1 * NBIN + k]);
      float2 N = make_float2(0.5f * (z1.x + z2.x) * en, 0.5f * (z1.y - z2.y) * en);
      float2 P = make_float2(0.5f * (z1.y + z2.y),      0.5f * (z2.x - z1.x));
      float2 PM = cmul(P, sMP1[k]);
      float2 s1 = make_float2(N.x + PM.x, N.y + PM.y);
      float2 s0 = sS0[k];
      if (k == 0 || k == 512) { s0.y = 0.0f; s1.y = 0.0f; }   // irfft drops these
      WA[SW(k)] = make_float2(s0.x - s1.y, s0.y + s1.x);
      if (k > 0 && k < 512)
        WA[SW(1024 - k)] = make_float2(s0.x + s1.y, s1.x - s0.y);
    }
  }
  __syncthreads();

  // ---- FFT5: packed synthesis iFFT (copy loader from WA) ----
  fftg2<true>(WB, WA, tt, [&](int n, int q) {
    return WA[SW(n)];
  });                                      // out: WB

  #pragma unroll
  for (int q = 0; q < 8; q++) {
    int n = tt + 128 * q;
    float wsc = (1.0f / 1024.0f) * g_w[n];
    float2 v = WB[SW(n)];
    g_frames[(size_t)f0 * 1024 + n] = v.x * wsc;
    g_frames[(size_t)f1 * 1024 + n] = v.y * wsc;
  }
}

// ----------------------------- overlap-add + wsq -------------------------------
__global__ void k_ola(float* __restrict__ out) {
  int i = blockIdx.x * blockDim.x + threadIdx.x;
  if (i >= OUTLEN) return;
  int p = i + 512;
  if (i >= 256 && i < OUTLEN - 256) {          // interior: exactly 4 full frames
    int jhi = p >> 8;
    int n0 = p & 255;
    const float* base = g_frames + (size_t)(jhi - 3) * 1024;
    float acc = base[n0 + 768];
    acc += base[1024 + n0 + 512];
    acc += base[2048 + n0 + 256];
    acc += base[3072 + n0];
    out[i] = acc * g_wsqinv[n0];
  } else {
    int jhi = p >> 8;
    int jlo = jhi - 3;
    if (jlo < 0) jlo = 0;
    if (jhi > NFR - 1) jhi = NFR - 1;
    float acc = 0.0f, wsq = 0.0f;
    for (int j = jlo; j <= jhi; j++) {
      int n = p - (j << 8);
      acc += g_frames[(size_t)j * 1024 + n];
      float w = g_w[n];
      wsq += w * w;
    }
    out[i] = acc / fmaxf(wsq, 1e-11f);
  }
}

// --------------------------------- launcher ------------------------------------
extern "C" void kernel_launch(void* const* d_in, const int* in_sizes, int n_in,
                              void* d_out, int out_size) {
  const float* log_f0  = (const float*)d_in[0];
  const float* env_noi = (const float*)d_in[1];
  const float* env_per = (const float*)d_in[2];
  const float* noise   = (const float*)d_in[3];
  float* out = (float*)d_out;

  k_init<<<1, 1024>>>();
  k_exp<<<NFR / 256, 256>>>(log_f0);
  k_scan_lo<<<NSIG / 1024, 256>>>();
  k_scan_hi<<<1, 1024>>>();
  k_sawimp<<<NSIG / 256, 256>>>();
  dim3 tb(32, 32);
  dim3 tg(NFR / 32, (NBIN + 31) / 32);
  k_transpose2<<<tg, tb>>>(env_noi, env_per);
  k_frames<<<NFR / 2, 128>>>(noise);
  k_ola<<<(OUTLEN + 255) / 256, 256>>>(out);
}

// round 13
// speedup vs baseline: 1.7528x; 1.2148x over previous
#include <cuda_runtime.h>
#include <math.h>

#define NSIG   (1 << 22)              // 4194304 = HOP * N_FRAMES
#define NFR    16384
#define NBIN   513
#define HOPSZ  256
#define OUTLEN ((NFR - 1) * HOPSZ)    // 4194048
#define LVOFF(l) ((1 << 22) - (1 << (23 - (l))))

// ------------------------- device scratch (static per rules) -------------------
__device__ float  g_f0up[NSIG];
__device__ float  g_lv[NSIG];                    // pair-sum levels 1..22 packed
__device__ float  g_pulse[NSIG];
__device__ float  g_envTn[(size_t)NFR * NBIN];   // transposed log-envelopes [t][k]
__device__ float  g_envTp[(size_t)NFR * NBIN];
__device__ float  g_frames[(size_t)NFR * 1024];  // windowed synthesis frames
__device__ float2 g_tw[256];                     // exp(-2*pi*i*t/1024), t<256
__device__ float  g_w[1024];                     // hann window
__device__ float  g_wsqinv[256];                 // 1/sum_k w^2(n0+256k), interior

// ---------------- fused: exp(log_f0) + linear interp + pair-sum levels 1..10 ----
// Per-sample arithmetic bit-identical to reference chain (expf/interp/__fadd_rn).
__global__ __launch_bounds__(256) void k_scan_lo(const float* __restrict__ log_f0) {
  __shared__ float s[256];
  __shared__ float sf0[6];
  int b = blockIdx.x, t = threadIdx.x;
  if (t < 6) {
    int idx = 4 * b - 1 + t;
    idx = max(0, min(16383, idx));
    sf0[t] = expf(log_f0[idx]);                 // same expf bits as reference
  }
  __syncthreads();
  float v[4];
  #pragma unroll
  for (int j = 0; j < 4; j++) {
    int i = b * 1024 + 4 * t + j;
    float fi  = (float)i;
    float pos = __fsub_rn(__fdiv_rn(__fadd_rn(fi, 0.5f), 256.0f), 0.5f);
    pos = fminf(fmaxf(pos, 0.0f), 16383.0f);
    float flo = floorf(pos);
    int lo = (int)flo;
    int hi = lo + 1; if (hi > 16383) hi = 16383;
    float frac = __fsub_rn(pos, flo);
    float flov = sf0[lo - (4 * b - 1)];
    float fhiv = sf0[hi - (4 * b - 1)];
    v[j] = __fadd_rn(__fmul_rn(flov, __fsub_rn(1.0f, frac)),
                     __fmul_rn(fhiv, frac));
  }
  ((float4*)g_f0up)[b * 256 + t] = make_float4(v[0], v[1], v[2], v[3]);
  float a0 = __fadd_rn(v[0], v[1]);
  float a1 = __fadd_rn(v[2], v[3]);
  float c  = __fadd_rn(a0, a1);
  ((float2*)(g_lv + LVOFF(1)))[b * 256 + t] = make_float2(a0, a1);
  g_lv[LVOFF(2) + b * 256 + t] = c;
  s[t] = c;
  __syncthreads();
  int n = 128;
  #pragma unroll
  for (int l = 3; l <= 10; l++) {
    float vv = 0.0f;
    if (t < n) vv = __fadd_rn(s[2 * t], s[2 * t + 1]);
    __syncthreads();
    if (t < n) { s[t] = vv; g_lv[LVOFF(l) + b * n + t] = vv; }
    __syncthreads();
    n >>= 1;
  }
}

// pair-sum levels 11..22, single block
__global__ __launch_bounds__(1024) void k_scan_hi() {
  __shared__ float s[4096];
  int t = threadIdx.x;
  #pragma unroll
  for (int q = 0; q < 4; q++) s[t + q * 1024] = g_lv[LVOFF(10) + t + q * 1024];
  __syncthreads();
  int n = 2048;
  for (int l = 11; l <= 22; l++) {
    float v0 = 0.0f, v1 = 0.0f;
    if (t < n)        v0 = __fadd_rn(s[2 * t], s[2 * t + 1]);
    if (t + 1024 < n) v1 = __fadd_rn(s[2 * (t + 1024)], s[2 * (t + 1024) + 1]);
    __syncthreads();
    if (t < n)        { s[t] = v0;        g_lv[LVOFF(l) + t] = v0; }
    if (t + 1024 < n) { s[t + 1024] = v1; g_lv[LVOFF(l) + t + 1024] = v1; }
    __syncthreads();
    n >>= 1;
  }
}

// cumsum closed form (jax associative_scan): left-fold of dyadic blocks of [0..n]
__device__ __forceinline__ float saw_at(int n) {
  int m = n + 1;
  float acc = 0.0f;
  bool first = true;
  int start = 0;
  #pragma unroll
  for (int l = 22; l >= 0; --l) {
    if (m & (1 << l)) {
      float v = (l == 0) ? g_f0up[start]
                         : g_lv[LVOFF(l) + (start >> l)];
      acc = first ? v : __fadd_rn(acc, v);
      first = false;
      start += (1 << l);
    }
  }
  float phase = __fdiv_rn(acc, 24000.0f);
  return __fsub_rn(phase, floorf(phase));
}

// ---- fused misc kernel: sawimp (blocks 0..16383) + transposes + table init -----
#define TPB_SAW   16384
#define TPB_TRANS 8704            // 512 x 17 tiles
__global__ __launch_bounds__(256) void k_misc(const float* __restrict__ in_n,
                                              const float* __restrict__ in_p) {
  __shared__ float sh[1056];      // max(257 saw, 32*33 tile)
  int bid = blockIdx.x;
  int t = threadIdx.x;

  if (bid < TPB_SAW) {
    // --------- saw + impulse (bit-critical path, unchanged arithmetic) ---------
    int base = bid * 256;
    sh[t] = saw_at(base + t);
    if (t == 0) sh[256] = saw_at((base + 256) & (NSIG - 1));
    __syncthreads();
    float d = __fdiv_rn(g_f0up[base + t], 24000.0f);
    g_pulse[base + t] = __fadd_rn(__fsub_rn(sh[t], sh[t + 1]), d);
  } else if (bid < TPB_SAW + TPB_TRANS) {
    // --------- envelope transposes [513][16384] -> [16384][513], both ---------
    int tb = bid - TPB_SAW;
    int t0 = (tb & 511) * 32;
    int k0 = (tb >> 9) * 32;
    int tx = t & 31, ty = t >> 5;          // 32 x 8
    float (*tile)[33] = (float(*)[33])sh;

    #pragma unroll
    for (int r = 0; r < 4; r++) {
      int yy = ty + 8 * r;
      if (k0 + yy < NBIN)
        tile[yy][tx] = in_n[(size_t)(k0 + yy) * NFR + t0 + tx];
    }
    __syncthreads();
    if (k0 + tx < NBIN) {
      #pragma unroll
      for (int r = 0; r < 4; r++) {
        int yy = ty + 8 * r;
        g_envTn[(size_t)(t0 + yy) * NBIN + k0 + tx] = tile[tx][yy];
      }
    }
    __syncthreads();
    #pragma unroll
    for (int r = 0; r < 4; r++) {
      int yy = ty + 8 * r;
      if (k0 + yy < NBIN)
        tile[yy][tx] = in_p[(size_t)(k0 + yy) * NFR + t0 + tx];
    }
    __syncthreads();
    if (k0 + tx < NBIN) {
      #pragma unroll
      for (int r = 0; r < 4; r++) {
        int yy = ty + 8 * r;
        g_envTp[(size_t)(t0 + yy) * NBIN + k0 + tx] = tile[tx][yy];
      }
    }
  } else {
    // ------------------------------ table init --------------------------------
    #pragma unroll
    for (int m = 0; m < 4; m++) {
      int i = t + 256 * m;
      g_w[i] = 0.5f * (1.0f - cosf((float)i * (6.28318530717958647692f / 1024.0f)));
    }
    {
      double ang = -2.0 * 3.14159265358979323846 * (double)t / 1024.0;
      g_tw[t] = make_float2((float)cos(ang), (float)sin(ang));
    }
    __syncthreads();
    float w3 = g_w[t + 768], w2 = g_w[t + 512], w1 = g_w[t + 256], w0 = g_w[t];
    float a = w3 * w3;
    a += w2 * w2;
    a += w1 * w1;
    a += w0 * w0;
    g_wsqinv[t] = 1.0f / fmaxf(a, 1e-11f);
  }
}

// ------------------------ register FFT building blocks -------------------------
__device__ __forceinline__ float2 cmul(float2 a, float2 b) {
  return make_float2(a.x * b.x - a.y * b.y, a.x * b.y + a.y * b.x);
}

template<bool INV>
__device__ __forceinline__ void dft4(float2& x0, float2& x1, float2& x2, float2& x3) {
  float t0x = x0.x + x2.x, t0y = x0.y + x2.y;
  float t1x = x0.x - x2.x, t1y = x0.y - x2.y;
  float t2x = x1.x + x3.x, t2y = x1.y + x3.y;
  float t3x = x1.x - x3.x, t3y = x1.y - x3.y;
  x0 = make_float2(t0x + t2x, t0y + t2y);
  x2 = make_float2(t0x - t2x, t0y - t2y);
  if (!INV) {
    x1 = make_float2(t1x + t3y, t1y - t3x);
    x3 = make_float2(t1x - t3y, t1y + t3x);
  } else {
    x1 = make_float2(t1x - t3y, t1y + t3x);
    x3 = make_float2(t1x + t3y, t1y - t3x);
  }
}

template<bool INV>
__device__ __forceinline__ void dft8(float2 c[8]) {
  const float R2 = 0.70710678118654752f;
  float2 e0 = c[0], e1 = c[2], e2 = c[4], e3 = c[6];
  float2 o0 = c[1], o1 = c[3], o2 = c[5], o3 = c[7];
  dft4<INV>(e0, e1, e2, e3);
  dft4<INV>(o0, o1, o2, o3);
  float2 T1, T2, T3;
  if (!INV) {
    T1 = make_float2(R2 * (o1.x + o1.y), R2 * (o1.y - o1.x));
    T2 = make_float2(o2.y, -o2.x);
    T3 = make_float2(R2 * (o3.y - o3.x), R2 * (-o3.x - o3.y));
  } else {
    T1 = make_float2(R2 * (o1.x - o1.y), R2 * (o1.y + o1.x));
    T2 = make_float2(-o2.y, o2.x);
    T3 = make_float2(R2 * (-o3.y - o3.x), R2 * (o3.x - o3.y));
  }
  c[0] = make_float2(e0.x + o0.x, e0.y + o0.y);
  c[4] = make_float2(e0.x - o0.x, e0.y - o0.y);
  c[1] = make_float2(e1.x + T1.x, e1.y + T1.y);
  c[5] = make_float2(e1.x - T1.x, e1.y - T1.y);
  c[2] = make_float2(e2.x + T2.x, e2.y + T2.y);
  c[6] = make_float2(e2.x - T2.x, e2.y - T2.y);
  c[3] = make_float2(e3.x + T3.x, e3.y + T3.y);
  c[7] = make_float2(e3.x - T3.x, e3.y - T3.y);
}

template<bool INV>
__device__ __forceinline__ void dft16(float2 c[16]) {
  const float C1 = 0.92387953251128676f;
  const float S1 = 0.38268343236508977f;
  const float R2 = 0.70710678118654752f;
  const float SG = INV ? -1.0f : 1.0f;
  float2 e[8], o[8];
  #pragma unroll
  for (int q = 0; q < 8; q++) { e[q] = c[2 * q]; o[q] = c[2 * q + 1]; }
  dft8<INV>(e);
  dft8<INV>(o);
  const float2 w[8] = {
    make_float2(1.0f, 0.0f),   make_float2(C1, -SG * S1),
    make_float2(R2, -SG * R2), make_float2(S1, -SG * C1),
    make_float2(0.0f, -SG),    make_float2(-S1, -SG * C1),
    make_float2(-R2, -SG * R2), make_float2(-C1, -SG * S1)};
  #pragma unroll
  for (int r = 0; r < 8; r++) {
    float2 T = cmul(o[r], w[r]);
    c[r]     = make_float2(e[r].x + T.x, e[r].y + T.y);
    c[r + 8] = make_float2(e[r].x - T.x, e[r].y - T.y);
  }
}

__device__ __forceinline__ int SW(int i) { return i + (i >> 4); }
#define WSN 1088

// 1024-pt FFT, 128 threads. Stage 1 inputs from loader functor.
// stage1 -> X, stage2 -> Y, stage3 -> X. Loader may read Y elementwise.
template<bool INV, class LD>
__device__ __forceinline__ void fftg2(float2* X, float2* Y, int t, LD ld) {
  { // stage 1: radix-8, m=1, j=t
    float2 c[8];
    #pragma unroll
    for (int q = 0; q < 8; q++) c[q] = ld(t + 128 * q, q);
    dft8<INV>(c);
    float2 w0 = __ldg(&g_tw[t]);
    float2 w1 = make_float2(w0.x, INV ? -w0.y : w0.y);
    float2 w2 = cmul(w1, w1);
    float2 w3 = cmul(w1, w2);
    float2 w4 = cmul(w2, w2);
    float2 w5 = cmul(w2, w3);
    float2 w6 = cmul(w3, w3);
    float2 w7 = cmul(w3, w4);
    c[1] = cmul(c[1], w1);
    c[2] = cmul(c[2], w2);
    c[3] = cmul(c[3], w3);
    c[4] = cmul(c[4], w4);
    c[5] = cmul(c[5], w5);
    c[6] = cmul(c[6], w6);
    c[7] = cmul(c[7], w7);
    #pragma unroll
    for (int r = 0; r < 8; r++) X[SW(8 * t + r)] = c[r];
  }
  __syncthreads();
  { // stage 2: radix-8, m=8
    float2 c[8];
    #pragma unroll
    for (int q = 0; q < 8; q++) c[q] = X[SW(t + 128 * q)];
    dft8<INV>(c);
    int j = t >> 3, k = t & 7;
    float2 w0 = __ldg(&g_tw[8 * j]);
    float2 w1 = make_float2(w0.x, INV ? -w0.y : w0.y);
    float2 w2 = cmul(w1, w1);
    float2 w3 = cmul(w1, w2);
    float2 w4 = cmul(w2, w2);
    float2 w5 = cmul(w2, w3);
    float2 w6 = cmul(w3, w3);
    float2 w7 = cmul(w3, w4);
    c[1] = cmul(c[1], w1);
    c[2] = cmul(c[2], w2);
    c[3] = cmul(c[3], w3);
    c[4] = cmul(c[4], w4);
    c[5] = cmul(c[5], w5);
    c[6] = cmul(c[6], w6);
    c[7] = cmul(c[7], w7);
    int o = k + 64 * j;
    #pragma unroll
    for (int r = 0; r < 8; r++) Y[SW(o + 8 * r)] = c[r];
  }
  __syncthreads();
  if (t < 64) { // stage 3: radix-16, m=64, j=0 -> no twiddles
    float2 c[16];
    #pragma unroll
    for (int q = 0; q < 16; q++) c[q] = Y[SW(t + 64 * q)];
    dft16<INV>(c);
    #pragma unroll
    for (int r = 0; r < 16; r++) X[SW(t + 64 * r)] = c[r];
  }
  __syncthreads();
}

// ------------------------------ per-frame-pair kernel ---------------------------
__global__ __launch_bounds__(128, 7) void k_frames(const float* __restrict__ noise) {
  __shared__ __align__(16) float2 WA[WSN];
  __shared__ __align__(16) float2 WB[WSN];
  __shared__ float2 sS0[NBIN];
  __shared__ float2 sMP1[NBIN];

  int tt = threadIdx.x;                   // 0..127
  int f0 = 2 * blockIdx.x;
  int f1 = f0 + 1;
  const float* ep0 = g_envTp + (size_t)f0 * NBIN;
  const float* ep1 = g_envTp + (size_t)f1 * NBIN;

  // ---- FFT1: packed min-phase iDFT of symmetric log-envelopes (direct load) ----
  fftg2<true>(WA, WB, tt, [&](int n, int q) {
    int k = (n <= 512) ? n : 1024 - n;
    return make_float2(ep0[k], ep1[k]);
  });                                      // out: WA = cep*1024 (packed)

  // ---- FFT2: forward FFT of odd cepstrum part (fold fused into loader) ----
  fftg2<false>(WB, WA, tt, [&](int n, int q) {
    float s = (n == 0 || n == 512) ? 0.0f
            : (n < 512 ? (1.0f / 1024.0f) : (-1.0f / 1024.0f));
    float2 v = WA[SW(n)];
    return make_float2(v.x * s, v.y * s);
  });                                      // out: WB, U[k] = -h1[k] + i*h0[k]

  // ---- min-phase exp -> per-thread smem (MP0 parks in sS0) ----
  #pragma unroll
  for (int q = 0; q < 5; q++) {
    int k = tt + 128 * q;
    if (k <= 512) {
      float2 U = WB[SW(k)];
      float sn, cs;
      float m0 = __expf(ep0[k]);
      __sincosf(U.y, &sn, &cs);
      sS0[k] = make_float2(m0 * cs, m0 * sn);
      float m1 = __expf(ep1[k]);
      __sincosf(-U.x, &sn, &cs);
      sMP1[k] = make_float2(m1 * cs, m1 * sn);
    }
  }

  // ---- FFT3: analysis of frame f0 (noise + i*pulse, direct load) ----
  fftg2<false>(WA, WB, tt, [&](int n, int q) {
    int gi = f0 * 256 - 256 + n;
    if (gi < 0) gi = -gi;
    else if (gi >= NSIG) gi = 2 * NSIG - 2 - gi;
    float w = g_w[n];
    return make_float2(noise[gi] * w, g_pulse[gi] * w);
  });                                      // out: WA

  #pragma unroll
  for (int q = 0; q < 5; q++) {
    int k = tt + 128 * q;
    if (k <= 512) {
      float2 z1 = WA[SW(k)];
      float2 z2 = WA[SW((1024 - k) & 1023)];
      float en = __expf(g_envTn[(size_t)f0 * NBIN + k]);
      float2 N = make_float2(0.5f * (z1.x + z2.x) * en, 0.5f * (z1.y - z2.y) * en);
      float2 P = make_float2(0.5f * (z1.y + z2.y),      0.5f * (z2.x - z1.x));
      float2 PM = cmul(P, sS0[k]);
      sS0[k] = make_float2(N.x + PM.x, N.y + PM.y);
    }
  }

  // ---- FFT4: analysis of frame f1 ----
  fftg2<false>(WB, WA, tt, [&](int n, int q) {
    int gi = f1 * 256 - 256 + n;
    if (gi < 0) gi = -gi;
    else if (gi >= NSIG) gi = 2 * NSIG - 2 - gi;
    float w = g_w[n];
    return make_float2(noise[gi] * w, g_pulse[gi] * w);
  });                                      // out: WB

  // ---- combine + build packed synthesis spectrum into WA ----
  #pragma unroll
  for (int q = 0; q < 5; q++) {
    int k = tt + 128 * q;
    if (k <= 512) {
      float2 z1 = WB[SW(k)];
      float2 z2 = WB[SW((1024 - k) & 1023)];
      float en = __expf(g_envTn[(size_t)f1 * NBIN + k]);
      float2 N = make_float2(0.5f * (z1.x + z2.x) * en, 0.5f * (z1.y - z2.y) * en);
      float2 P = make_float2(0.5f * (z1.y + z2.y),      0.5f * (z2.x - z1.x));
      float2 PM = cmul(P, sMP1[k]);
      float2 s1 = make_float2(N.x + PM.x, N.y + PM.y);
      float2 s0 = sS0[k];
      if (k == 0 || k == 512) { s0.y = 0.0f; s1.y = 0.0f; }   // irfft drops these
      WA[SW(k)] = make_float2(s0.x - s1.y, s0.y + s1.x);
      if (k > 0 && k < 512)
        WA[SW(1024 - k)] = make_float2(s0.x + s1.y, s1.x - s0.y);
    }
  }
  __syncthreads();

  // ---- FFT5: packed synthesis iFFT (copy loader from WA) ----
  fftg2<true>(WB, WA, tt, [&](int n, int q) {
    return WA[SW(n)];
  });                                      // out: WB

  #pragma unroll
  for (int q = 0; q < 8; q++) {
    int n = tt + 128 * q;
    float wsc = (1.0f / 1024.0f) * g_w[n];
    float2 v = WB[SW(n)];
    g_frames[(size_t)f0 * 1024 + n] = v.x * wsc;
    g_frames[(size_t)f1 * 1024 + n] = v.y * wsc;
  }
}

// ----------------------------- overlap-add + wsq (float4) ----------------------
__global__ void k_ola(float* __restrict__ out) {
  int c = blockIdx.x * blockDim.x + threadIdx.x;
  int i0 = 4 * c;
  if (i0 >= OUTLEN) return;
  if (i0 >= 256 && i0 + 4 <= OUTLEN - 256) {   // interior: 4 full frames, one row
    int p0 = i0 + 512;
    int jhi = p0 >> 8;
    int n0 = p0 & 255;
    const float* base = g_frames + (size_t)(jhi - 3) * 1024;
    float4 a0 = *(const float4*)(base + 768 + n0);
    float4 a1 = *(const float4*)(base + 1024 + 512 + n0);
    float4 a2 = *(const float4*)(base + 2048 + 256 + n0);
    float4 a3 = *(const float4*)(base + 3072 + n0);
    float4 wi = *(const float4*)(g_wsqinv + n0);
    float4 r;
    r.x = ((a0.x + a1.x) + a2.x + a3.x) * wi.x;
    r.y = ((a0.y + a1.y) + a2.y + a3.y) * wi.y;
    r.z = ((a0.z + a1.z) + a2.z + a3.z) * wi.z;
    r.w = ((a0.w + a1.w) + a2.w + a3.w) * wi.w;
    ((float4*)out)[c] = r;
  } else {
    #pragma unroll
    for (int u = 0; u < 4; u++) {
      int i = i0 + u;
      if (i >= OUTLEN) break;
      int p = i + 512;
      int jhi = p >> 8;
      int jlo = jhi - 3;
      if (jlo < 0) jlo = 0;
      if (jhi > NFR - 1) jhi = NFR - 1;
      float acc = 0.0f, wsq = 0.0f;
      for (int j = jlo; j <= jhi; j++) {
        int n = p - (j << 8);
        acc += g_frames[(size_t)j * 1024 + n];
        float w = g_w[n];
        wsq += w * w;
      }
      out[i] = acc / fmaxf(wsq, 1e-11f);
    }
  }
}

// --------------------------------- launcher ------------------------------------
extern "C" void kernel_launch(void* const* d_in, const int* in_sizes, int n_in,
                              void* d_out, int out_size) {
  const float* log_f0  = (const float*)d_in[0];
  const float* env_noi = (const float*)d_in[1];
  const float* env_per = (const float*)d_in[2];
  const float* noise   = (const float*)d_in[3];
  float* out = (float*)d_out;

  k_scan_lo<<<NSIG / 1024, 256>>>(log_f0);
  k_scan_hi<<<1, 1024>>>();
  k_misc<<<TPB_SAW + TPB_TRANS + 1, 256>>>(env_noi, env_per);
  k_frames<<<NFR / 2, 128>>>(noise);
  k_ola<<<(OUTLEN / 4 + 255) / 256, 256>>>(out);
}